// round 2
// baseline (speedup 1.0000x reference)
#include <cuda_runtime.h>
#include <cuda_bf16.h>
#include <cstdint>

// ---------------------------------------------------------------------------
// SwinBlock: LN1 -> (shift+window) -> KV gemm / Q gemm -> windowed attention
//            -> proj gemm (+residual, reverse shift/window) -> LN2
//            -> fc1+gelu -> fc2 (+residual) 
// All big GEMMs: mma.sync tf32 (rna-rounded), fp32 accumulate.
// ---------------------------------------------------------------------------

#define TOK   65536           // B * H * W = 16*64*64
#define CEMB  512
#define FFN   2048

// scratch (static device arrays; allocation-free rule)
__device__ float g_lnx   [ (size_t)TOK * CEMB ];   // LN1(x) window order; reused as LN2 out
__device__ float g_lnskip[ (size_t)TOK * CEMB ];   // LN1(skip) window order; reused as attn out
__device__ float g_kv    [ (size_t)TOK * 1024 ];   // k (cols 0..511) | v (cols 512..1023)
__device__ float g_q     [ (size_t)TOK * CEMB ];
__device__ float g_xres  [ (size_t)TOK * CEMB ];   // identity + attn proj (natural order)
__device__ float g_h     [ (size_t)TOK * FFN  ];   // gelu(fc1) activations

// window-token index -> natural token index (handles shift roll both ways)
__device__ __forceinline__ int wt_to_nat(int wt) {
    int n   = wt & 63;
    int win = wt >> 6;
    int wi  = win & 63;
    int b   = win >> 6;
    int hp  = ((wi >> 3) << 3) + (n >> 3);
    int wp  = ((wi & 7)  << 3) + (n & 7);
    int h   = (hp + 4) & 63;
    int w   = (wp + 4) & 63;
    return (b << 12) + (h << 6) + w;
}

__device__ __forceinline__ float tf32r(float x) {
    uint32_t u;
    asm("cvt.rna.tf32.f32 %0, %1;" : "=r"(u) : "f"(x));
    return __uint_as_float(u);
}

__device__ __forceinline__ void mma8(float c[4], const uint32_t a[4], const uint32_t b[2]) {
    asm volatile(
        "mma.sync.aligned.m16n8k8.row.col.f32.tf32.tf32.f32 "
        "{%0,%1,%2,%3}, {%4,%5,%6,%7}, {%8,%9}, {%0,%1,%2,%3};\n"
        : "+f"(c[0]), "+f"(c[1]), "+f"(c[2]), "+f"(c[3])
        : "r"(a[0]), "r"(a[1]), "r"(a[2]), "r"(a[3]), "r"(b[0]), "r"(b[1]));
}

// ---------------------------------------------------------------------------
// LayerNorm (one warp per row of 512)
// ---------------------------------------------------------------------------
__device__ __forceinline__ void ln_row(const float* __restrict__ in,
                                       const float* __restrict__ g,
                                       const float* __restrict__ b,
                                       float* __restrict__ out, int lane) {
    float4 v[4];
    float s = 0.f, sq = 0.f;
#pragma unroll
    for (int j = 0; j < 4; j++) {
        v[j] = *(const float4*)(in + (((j << 5) + lane) << 2));
        s  += v[j].x + v[j].y + v[j].z + v[j].w;
        sq += v[j].x*v[j].x + v[j].y*v[j].y + v[j].z*v[j].z + v[j].w*v[j].w;
    }
#pragma unroll
    for (int o = 16; o; o >>= 1) {
        s  += __shfl_xor_sync(0xffffffffu, s, o);
        sq += __shfl_xor_sync(0xffffffffu, sq, o);
    }
    float mean = s * (1.f / 512.f);
    float var  = sq * (1.f / 512.f) - mean * mean;
    float rstd = rsqrtf(var + 1e-5f);
#pragma unroll
    for (int j = 0; j < 4; j++) {
        int off = (((j << 5) + lane) << 2);
        float4 gg = *(const float4*)(g + off);
        float4 bb = *(const float4*)(b + off);
        float4 o4;
        o4.x = (v[j].x - mean) * rstd * gg.x + bb.x;
        o4.y = (v[j].y - mean) * rstd * gg.y + bb.y;
        o4.z = (v[j].z - mean) * rstd * gg.z + bb.z;
        o4.w = (v[j].w - mean) * rstd * gg.w + bb.w;
        *(float4*)(out + off) = o4;
    }
}

__global__ __launch_bounds__(256) void ln1_kernel(const float* __restrict__ x,
                                                  const float* __restrict__ skip,
                                                  const float* __restrict__ g1,
                                                  const float* __restrict__ b1,
                                                  float* __restrict__ outx,
                                                  float* __restrict__ outs) {
    int warp = threadIdx.x >> 5, lane = threadIdx.x & 31;
    int wt   = (blockIdx.x << 3) + warp;
    int nat  = wt_to_nat(wt);
    ln_row(x    + (size_t)nat * CEMB, g1, b1, outx + (size_t)wt * CEMB, lane);
    ln_row(skip + (size_t)nat * CEMB, g1, b1, outs + (size_t)wt * CEMB, lane);
}

__global__ __launch_bounds__(256) void ln2_kernel(const float* __restrict__ xin,
                                                  const float* __restrict__ g2,
                                                  const float* __restrict__ b2,
                                                  float* __restrict__ out) {
    int warp = threadIdx.x >> 5, lane = threadIdx.x & 31;
    int row  = (blockIdx.x << 3) + warp;
    ln_row(xin + (size_t)row * CEMB, g2, b2, out + (size_t)row * CEMB, lane);
}

// ---------------------------------------------------------------------------
// Tiled tf32 GEMM:  out[M,N] = A[M,K] @ W[N,K]^T  (+ epilogue)
// BM=128 BN=128 BK=16, 256 threads, 8 warps (2 x 4), warp tile 64x32
// EPI: 0 plain+bias | 1 (x+bias)*SCALE | 2 proj residual scatter
//      3 bias+gelu  | 4 final residual
// ---------------------------------------------------------------------------
template <int EPI>
__global__ __launch_bounds__(256) void gemm_tf32(const float* __restrict__ A,
                                                 const float* __restrict__ W,
                                                 const float* __restrict__ bias,
                                                 float* __restrict__ out,
                                                 const float* __restrict__ res,
                                                 int M, int N, int K) {
    __shared__ float As[16][136];
    __shared__ float Bs[16][136];

    const int tid = threadIdx.x;
    const int bm  = blockIdx.y * 128;
    const int bn  = blockIdx.x * 128;

    const int lane = tid & 31, wid = tid >> 5;
    const int wm  = (wid & 1) * 64;
    const int wnn = (wid >> 1) * 32;
    const int g   = lane >> 2, tq = lane & 3;

    float acc[4][4][4] = {};

    for (int k0 = 0; k0 < K; k0 += 16) {
#pragma unroll
        for (int it = 0; it < 2; it++) {
            int idx = tid + it * 256;
            int r = idx >> 2, c4 = (idx & 3) << 2;
            float4 va = *(const float4*)(A + (size_t)(bm + r) * K + k0 + c4);
            As[c4 + 0][r] = tf32r(va.x);
            As[c4 + 1][r] = tf32r(va.y);
            As[c4 + 2][r] = tf32r(va.z);
            As[c4 + 3][r] = tf32r(va.w);
            float4 vb = *(const float4*)(W + (size_t)(bn + r) * K + k0 + c4);
            Bs[c4 + 0][r] = tf32r(vb.x);
            Bs[c4 + 1][r] = tf32r(vb.y);
            Bs[c4 + 2][r] = tf32r(vb.z);
            Bs[c4 + 3][r] = tf32r(vb.w);
        }
        __syncthreads();

#pragma unroll
        for (int kk = 0; kk < 2; kk++) {
            uint32_t af[4][4];
#pragma unroll
            for (int mi = 0; mi < 4; mi++) {
                int m = wm + mi * 16 + g;
                af[mi][0] = __float_as_uint(As[kk * 8 + tq    ][m]);
                af[mi][1] = __float_as_uint(As[kk * 8 + tq    ][m + 8]);
                af[mi][2] = __float_as_uint(As[kk * 8 + tq + 4][m]);
                af[mi][3] = __float_as_uint(As[kk * 8 + tq + 4][m + 8]);
            }
            uint32_t bfr[4][2];
#pragma unroll
            for (int ni = 0; ni < 4; ni++) {
                int n = wnn + ni * 8 + g;
                bfr[ni][0] = __float_as_uint(Bs[kk * 8 + tq    ][n]);
                bfr[ni][1] = __float_as_uint(Bs[kk * 8 + tq + 4][n]);
            }
#pragma unroll
            for (int mi = 0; mi < 4; mi++)
#pragma unroll
                for (int ni = 0; ni < 4; ni++)
                    mma8(acc[mi][ni], af[mi], bfr[ni]);
        }
        __syncthreads();
    }

    // epilogue
#pragma unroll
    for (int mi = 0; mi < 4; mi++) {
#pragma unroll
        for (int ni = 0; ni < 4; ni++) {
            int c0 = bn + wnn + ni * 8 + (tq << 1);
            float bv0 = bias[c0], bv1 = bias[c0 + 1];
#pragma unroll
            for (int half = 0; half < 2; half++) {
                int r = bm + wm + mi * 16 + g + half * 8;
                float v0 = acc[mi][ni][half * 2 + 0] + bv0;
                float v1 = acc[mi][ni][half * 2 + 1] + bv1;
                if (EPI == 0) {
                    size_t o = (size_t)r * N + c0;
                    out[o] = v0; out[o + 1] = v1;
                } else if (EPI == 1) {
                    const float sc = 0.17677669529663687f;  // 32^-0.5
                    size_t o = (size_t)r * N + c0;
                    out[o] = v0 * sc; out[o + 1] = v1 * sc;
                } else if (EPI == 2) {
                    int nat = wt_to_nat(r);
                    size_t o = (size_t)nat * CEMB + c0;
                    out[o]     = res[o]     + v0;
                    out[o + 1] = res[o + 1] + v1;
                } else if (EPI == 3) {
                    size_t o = (size_t)r * N + c0;
                    out[o]     = 0.5f * v0 * (1.f + erff(v0 * 0.70710678118654752f));
                    out[o + 1] = 0.5f * v1 * (1.f + erff(v1 * 0.70710678118654752f));
                } else {  // EPI == 4
                    size_t o = (size_t)r * N + c0;
                    out[o]     = res[o]     + v0;
                    out[o + 1] = res[o + 1] + v1;
                }
            }
        }
    }
}

// ---------------------------------------------------------------------------
// Windowed attention: one CTA per window (1024 windows), loop 16 heads.
// scores = q k^T + rel_bias + mask; softmax; out = scores @ v
// ---------------------------------------------------------------------------
__global__ __launch_bounds__(256) void attn_kernel(const float* __restrict__ q,
                                                   const float* __restrict__ kv,
                                                   const float* __restrict__ rb,
                                                   float* __restrict__ out) {
    __shared__ __align__(16) float sq [64][36];
    __shared__ __align__(16) float skT[32][68];
    __shared__ __align__(16) float sv [64][36];
    __shared__ float sc[64][65];

    const int tid = threadIdx.x;
    const int win = blockIdx.x;
    const int wi  = win & 63;
    const int wr  = wi >> 3, wc = wi & 7;
    const int base = win << 6;

    for (int h = 0; h < 16; h++) {
        // load q/k/v head tiles
        for (int i = tid; i < 2048; i += 256) {
            int n = i >> 5, d = i & 31;
            sq[n][d] = q [(size_t)(base + n) * 512  + h * 32 + d];
            skT[d][n]= kv[(size_t)(base + n) * 1024 + h * 32 + d];
            sv[n][d] = kv[(size_t)(base + n) * 1024 + 512 + h * 32 + d];
        }
        __syncthreads();

        // scores: each thread a 4x4 tile
        const int tn = (tid >> 4) << 2;
        const int tm = (tid & 15) << 2;
        float rs[4][4] = {};
        for (int dc = 0; dc < 32; dc += 4) {
            float a[4][4], bb[4][4];
#pragma unroll
            for (int i = 0; i < 4; i++)
                *(float4*)a[i] = *(const float4*)&sq[tn + i][dc];
#pragma unroll
            for (int l = 0; l < 4; l++)
                *(float4*)bb[l] = *(const float4*)&skT[dc + l][tm];
#pragma unroll
            for (int i = 0; i < 4; i++)
#pragma unroll
                for (int j = 0; j < 4; j++)
#pragma unroll
                    for (int l = 0; l < 4; l++)
                        rs[i][j] += a[i][l] * bb[l][j];
        }
#pragma unroll
        for (int i = 0; i < 4; i++) {
            int n = tn + i;
            int cn = 15 * (n >> 3) + (n & 7);
            int rhn = (wr == 7) ? (((n >> 3) < 4) ? 1 : 2) : 0;
            int rwn = (wc == 7) ? (((n & 7)  < 4) ? 1 : 2) : 0;
            int regn = rhn * 3 + rwn;
#pragma unroll
            for (int j = 0; j < 4; j++) {
                int m = tm + j;
                int m2 = 63 - m;
                int cm = 15 * (m2 >> 3) + (m2 & 7);
                float bv = rb[(cn + cm) * 16 + h];
                int rhm = (wr == 7) ? (((m >> 3) < 4) ? 1 : 2) : 0;
                int rwm = (wc == 7) ? (((m & 7)  < 4) ? 1 : 2) : 0;
                float msk = ((rhm * 3 + rwm) != regn) ? -100.f : 0.f;
                sc[n][m] = rs[i][j] + bv + msk;
            }
        }
        __syncthreads();

        // softmax: quad of threads per row
        {
            int row = tid >> 2, sub = tid & 3;
            float mx = -1e30f;
#pragma unroll
            for (int j = 0; j < 16; j++) mx = fmaxf(mx, sc[row][sub + 4 * j]);
            mx = fmaxf(mx, __shfl_xor_sync(0xffffffffu, mx, 1));
            mx = fmaxf(mx, __shfl_xor_sync(0xffffffffu, mx, 2));
            float ev[16], sm = 0.f;
#pragma unroll
            for (int j = 0; j < 16; j++) {
                ev[j] = expf(sc[row][sub + 4 * j] - mx);
                sm += ev[j];
            }
            sm += __shfl_xor_sync(0xffffffffu, sm, 1);
            sm += __shfl_xor_sync(0xffffffffu, sm, 2);
            float inv = 1.f / sm;
#pragma unroll
            for (int j = 0; j < 16; j++) sc[row][sub + 4 * j] = ev[j] * inv;
        }
        __syncthreads();

        // out = scores @ v : thread computes 2 rows x 4 cols
        {
            int n0 = (tid >> 3) << 1;
            int d0 = (tid & 7) << 2;
            float o0[4] = {}, o1[4] = {};
            for (int m = 0; m < 64; m++) {
                float4 vv = *(const float4*)&sv[m][d0];
                float s0 = sc[n0][m], s1 = sc[n0 + 1][m];
                o0[0] += s0 * vv.x; o0[1] += s0 * vv.y; o0[2] += s0 * vv.z; o0[3] += s0 * vv.w;
                o1[0] += s1 * vv.x; o1[1] += s1 * vv.y; o1[2] += s1 * vv.z; o1[3] += s1 * vv.w;
            }
            float4 w0 = make_float4(o0[0], o0[1], o0[2], o0[3]);
            float4 w1 = make_float4(o1[0], o1[1], o1[2], o1[3]);
            *(float4*)&out[(size_t)(base + n0)     * 512 + h * 32 + d0] = w0;
            *(float4*)&out[(size_t)(base + n0 + 1) * 512 + h * 32 + d0] = w1;
        }
        __syncthreads();
    }
}

// ---------------------------------------------------------------------------
extern "C" void kernel_launch(void* const* d_in, const int* in_sizes, int n_in,
                              void* d_out, int out_size) {
    const float* x      = (const float*)d_in[0];
    const float* skip   = (const float*)d_in[1];
    const float* n1g    = (const float*)d_in[2];
    const float* n1b    = (const float*)d_in[3];
    const float* w_qkv  = (const float*)d_in[4];
    const float* b_qkv  = (const float*)d_in[5];
    const float* w_skip = (const float*)d_in[6];
    const float* b_skip = (const float*)d_in[7];
    const float* relb   = (const float*)d_in[8];
    const float* w_proj = (const float*)d_in[9];
    const float* b_proj = (const float*)d_in[10];
    const float* n2g    = (const float*)d_in[11];
    const float* n2b    = (const float*)d_in[12];
    const float* w_fc1  = (const float*)d_in[13];
    const float* b_fc1  = (const float*)d_in[14];
    const float* w_fc2  = (const float*)d_in[15];
    const float* b_fc2  = (const float*)d_in[16];
    float* outp = (float*)d_out;

    float *lnx, *lnskip, *kvb, *qb, *xres, *hb;
    cudaGetSymbolAddress((void**)&lnx,    g_lnx);
    cudaGetSymbolAddress((void**)&lnskip, g_lnskip);
    cudaGetSymbolAddress((void**)&kvb,    g_kv);
    cudaGetSymbolAddress((void**)&qb,     g_q);
    cudaGetSymbolAddress((void**)&xres,   g_xres);
    cudaGetSymbolAddress((void**)&hb,     g_h);

    // 1) LN1 of x and skip, gathered into shifted-window order
    ln1_kernel<<<8192, 256>>>(x, skip, n1g, n1b, lnx, lnskip);
    // 2) kv = lnx @ w_qkv^T + b_qkv   (N=1024: k|v)
    gemm_tf32<0><<<dim3(8, 512), 256>>>(lnx, w_qkv, b_qkv, kvb, nullptr, TOK, 1024, 512);
    // 3) q  = (lnskip @ w_skip^T + b_skip) * scale
    gemm_tf32<1><<<dim3(4, 512), 256>>>(lnskip, w_skip, b_skip, qb, nullptr, TOK, 512, 512);
    // 4) windowed attention (writes attn out into lnskip buffer)
    attn_kernel<<<1024, 256>>>(qb, kvb, relb, lnskip);
    // 5) proj + residual, scattered back to natural order
    gemm_tf32<2><<<dim3(4, 512), 256>>>(lnskip, w_proj, b_proj, xres, x, TOK, 512, 512);
    // 6) LN2
    ln2_kernel<<<8192, 256>>>(xres, n2g, n2b, lnx);
    // 7) fc1 + gelu
    gemm_tf32<3><<<dim3(16, 512), 256>>>(lnx, w_fc1, b_fc1, hb, nullptr, TOK, FFN, 512);
    // 8) fc2 + final residual -> d_out
    gemm_tf32<4><<<dim3(4, 512), 256>>>(hb, w_fc2, b_fc2, outp, xres, TOK, 512, FFN);
    (void)in_sizes; (void)n_in; (void)out_size;
}

// round 4
// speedup vs baseline: 1.3960x; 1.3960x over previous
#include <cuda_runtime.h>
#include <cuda_bf16.h>
#include <cstdint>

// ---------------------------------------------------------------------------
// SwinBlock on sm_103a, round 2:
//   - GEMMs: tf32 mma.sync m16n8k8, BK=32, 3-stage cp.async pipeline,
//     [m][k]-major smem (pad 36), 2 CTAs/SM target.
//   - Attention: head loop split over gridDim.y.
// ---------------------------------------------------------------------------

#define TOK   65536
#define CEMB  512
#define FFN   2048

__device__ float g_lnx   [ (size_t)TOK * CEMB ];
__device__ float g_lnskip[ (size_t)TOK * CEMB ];
__device__ float g_kv    [ (size_t)TOK * 1024 ];
__device__ float g_q     [ (size_t)TOK * CEMB ];
__device__ float g_xres  [ (size_t)TOK * CEMB ];
__device__ float g_h     [ (size_t)TOK * FFN  ];

__device__ __forceinline__ int wt_to_nat(int wt) {
    int n   = wt & 63;
    int win = wt >> 6;
    int wi  = win & 63;
    int b   = win >> 6;
    int hp  = ((wi >> 3) << 3) + (n >> 3);
    int wp  = ((wi & 7)  << 3) + (n & 7);
    int h   = (hp + 4) & 63;
    int w   = (wp + 4) & 63;
    return (b << 12) + (h << 6) + w;
}

__device__ __forceinline__ uint32_t tf32u(float x) {
    uint32_t u;
    asm("cvt.rna.tf32.f32 %0, %1;" : "=r"(u) : "f"(x));
    return u;
}

__device__ __forceinline__ void mma8(float c[4], const uint32_t a[4], const uint32_t b[2]) {
    asm volatile(
        "mma.sync.aligned.m16n8k8.row.col.f32.tf32.tf32.f32 "
        "{%0,%1,%2,%3}, {%4,%5,%6,%7}, {%8,%9}, {%0,%1,%2,%3};\n"
        : "+f"(c[0]), "+f"(c[1]), "+f"(c[2]), "+f"(c[3])
        : "r"(a[0]), "r"(a[1]), "r"(a[2]), "r"(a[3]), "r"(b[0]), "r"(b[1]));
}

// ---------------------------------------------------------------------------
// LayerNorm (one warp per row of 512)
// ---------------------------------------------------------------------------
__device__ __forceinline__ void ln_row(const float* __restrict__ in,
                                       const float* __restrict__ g,
                                       const float* __restrict__ b,
                                       float* __restrict__ out, int lane) {
    float4 v[4];
    float s = 0.f, sq = 0.f;
#pragma unroll
    for (int j = 0; j < 4; j++) {
        v[j] = *(const float4*)(in + (((j << 5) + lane) << 2));
        s  += v[j].x + v[j].y + v[j].z + v[j].w;
        sq += v[j].x*v[j].x + v[j].y*v[j].y + v[j].z*v[j].z + v[j].w*v[j].w;
    }
#pragma unroll
    for (int o = 16; o; o >>= 1) {
        s  += __shfl_xor_sync(0xffffffffu, s, o);
        sq += __shfl_xor_sync(0xffffffffu, sq, o);
    }
    float mean = s * (1.f / 512.f);
    float var  = sq * (1.f / 512.f) - mean * mean;
    float rstd = rsqrtf(var + 1e-5f);
#pragma unroll
    for (int j = 0; j < 4; j++) {
        int off = (((j << 5) + lane) << 2);
        float4 gg = *(const float4*)(g + off);
        float4 bb = *(const float4*)(b + off);
        float4 o4;
        o4.x = (v[j].x - mean) * rstd * gg.x + bb.x;
        o4.y = (v[j].y - mean) * rstd * gg.y + bb.y;
        o4.z = (v[j].z - mean) * rstd * gg.z + bb.z;
        o4.w = (v[j].w - mean) * rstd * gg.w + bb.w;
        *(float4*)(out + off) = o4;
    }
}

__global__ __launch_bounds__(256) void ln1_kernel(const float* __restrict__ x,
                                                  const float* __restrict__ skip,
                                                  const float* __restrict__ g1,
                                                  const float* __restrict__ b1,
                                                  float* __restrict__ outx,
                                                  float* __restrict__ outs) {
    int warp = threadIdx.x >> 5, lane = threadIdx.x & 31;
    int wt   = (blockIdx.x << 3) + warp;
    int nat  = wt_to_nat(wt);
    ln_row(x    + (size_t)nat * CEMB, g1, b1, outx + (size_t)wt * CEMB, lane);
    ln_row(skip + (size_t)nat * CEMB, g1, b1, outs + (size_t)wt * CEMB, lane);
}

__global__ __launch_bounds__(256) void ln2_kernel(const float* __restrict__ xin,
                                                  const float* __restrict__ g2,
                                                  const float* __restrict__ b2,
                                                  float* __restrict__ out) {
    int warp = threadIdx.x >> 5, lane = threadIdx.x & 31;
    int row  = (blockIdx.x << 3) + warp;
    ln_row(xin + (size_t)row * CEMB, g2, b2, out + (size_t)row * CEMB, lane);
}

// ---------------------------------------------------------------------------
// Pipelined tf32 GEMM: out[M,N] = A[M,K] @ W[N,K]^T (+epilogue)
// BM=128 BN=128 BK=32, 3-stage cp.async, 256 thr, warp tile 64x32
// smem per stage: A[128][36] + B[128][36] floats
// ---------------------------------------------------------------------------
#define GSTAGES 3
#define STAGE_F 4608          // 128*36 floats per matrix per stage
#define GEMM_SMEM_BYTES (GSTAGES * STAGE_F * 2 * 4)

__device__ __forceinline__ void cpa16(uint32_t dst, const float* src) {
    asm volatile("cp.async.cg.shared.global [%0], [%1], 16;\n" :: "r"(dst), "l"(src));
}
__device__ __forceinline__ void cpa_commit() { asm volatile("cp.async.commit_group;\n"); }
__device__ __forceinline__ void cpa_wait1()  { asm volatile("cp.async.wait_group 1;\n"); }

template <int EPI>
__global__ __launch_bounds__(256, 2) void gemm_tf32(const float* __restrict__ A,
                                                    const float* __restrict__ W,
                                                    const float* __restrict__ bias,
                                                    float* __restrict__ out,
                                                    const float* __restrict__ res,
                                                    int M, int N, int K) {
    extern __shared__ float smem[];
    float* AsAll = smem;
    float* BsAll = smem + GSTAGES * STAGE_F;
    const uint32_t aBase = (uint32_t)__cvta_generic_to_shared(AsAll);
    const uint32_t bBase = (uint32_t)__cvta_generic_to_shared(BsAll);

    const int tid = threadIdx.x;
    const int bm  = blockIdx.y * 128;
    const int bn  = blockIdx.x * 128;

    const int lane = tid & 31, wid = tid >> 5;
    const int wm  = (wid & 1) * 64;
    const int wnn = (wid >> 1) * 32;
    const int g   = lane >> 2, tq = lane & 3;

    // per-thread load coords: 1024 float4 per matrix per stage, 4 per thread
    const int lrow0 = tid >> 3;          // +32 per j
    const int lc4   = (tid & 7) << 2;

    float acc[4][4][4] = {};

    const int nit = K >> 5;              // K/32

    auto load_stage = [&](int s, int k0) {
        uint32_t adst = aBase + (uint32_t)(s * STAGE_F) * 4;
        uint32_t bdst = bBase + (uint32_t)(s * STAGE_F) * 4;
#pragma unroll
        for (int j = 0; j < 4; j++) {
            int row = lrow0 + (j << 5);
            uint32_t soff = (uint32_t)(row * 36 + lc4) * 4;
            cpa16(adst + soff, A + (size_t)(bm + row) * K + k0 + lc4);
            cpa16(bdst + soff, W + (size_t)(bn + row) * K + k0 + lc4);
        }
    };

    load_stage(0, 0);  cpa_commit();
    load_stage(1, 32); cpa_commit();

    for (int it = 0; it < nit; it++) {
        cpa_wait1();
        __syncthreads();

        int nk = it + 2;
        if (nk < nit) load_stage(nk - (nk >= GSTAGES ? GSTAGES * (nk / GSTAGES) : 0) % GSTAGES == nk % GSTAGES ? nk % GSTAGES : nk % GSTAGES, nk << 5);
        cpa_commit();

        const float* as = AsAll + (it % GSTAGES) * STAGE_F;
        const float* bs = BsAll + (it % GSTAGES) * STAGE_F;

#pragma unroll
        for (int kk = 0; kk < 4; kk++) {
            const int kb = kk << 3;
            uint32_t af[4][4];
#pragma unroll
            for (int mi = 0; mi < 4; mi++) {
                int m = wm + mi * 16 + g;
                af[mi][0] = tf32u(as[m * 36 + kb + tq]);
                af[mi][1] = tf32u(as[(m + 8) * 36 + kb + tq]);
                af[mi][2] = tf32u(as[m * 36 + kb + tq + 4]);
                af[mi][3] = tf32u(as[(m + 8) * 36 + kb + tq + 4]);
            }
            uint32_t bfr[4][2];
#pragma unroll
            for (int ni = 0; ni < 4; ni++) {
                int n = wnn + ni * 8 + g;
                bfr[ni][0] = tf32u(bs[n * 36 + kb + tq]);
                bfr[ni][1] = tf32u(bs[n * 36 + kb + tq + 4]);
            }
#pragma unroll
            for (int mi = 0; mi < 4; mi++)
#pragma unroll
                for (int ni = 0; ni < 4; ni++)
                    mma8(acc[mi][ni], af[mi], bfr[ni]);
        }
        __syncthreads();
    }

    // epilogue
#pragma unroll
    for (int mi = 0; mi < 4; mi++) {
#pragma unroll
        for (int ni = 0; ni < 4; ni++) {
            int c0 = bn + wnn + ni * 8 + (tq << 1);
            float bv0 = bias[c0], bv1 = bias[c0 + 1];
#pragma unroll
            for (int half = 0; half < 2; half++) {
                int r = bm + wm + mi * 16 + g + half * 8;
                float v0 = acc[mi][ni][half * 2 + 0] + bv0;
                float v1 = acc[mi][ni][half * 2 + 1] + bv1;
                if (EPI == 0) {
                    size_t o = (size_t)r * N + c0;
                    out[o] = v0; out[o + 1] = v1;
                } else if (EPI == 1) {
                    const float sc = 0.17677669529663687f;
                    size_t o = (size_t)r * N + c0;
                    out[o] = v0 * sc; out[o + 1] = v1 * sc;
                } else if (EPI == 2) {
                    int nat = wt_to_nat(r);
                    size_t o = (size_t)nat * CEMB + c0;
                    out[o]     = res[o]     + v0;
                    out[o + 1] = res[o + 1] + v1;
                } else if (EPI == 3) {
                    size_t o = (size_t)r * N + c0;
                    out[o]     = 0.5f * v0 * (1.f + erff(v0 * 0.70710678118654752f));
                    out[o + 1] = 0.5f * v1 * (1.f + erff(v1 * 0.70710678118654752f));
                } else {
                    size_t o = (size_t)r * N + c0;
                    out[o]     = res[o]     + v0;
                    out[o + 1] = res[o + 1] + v1;
                }
            }
        }
    }
}

// ---------------------------------------------------------------------------
// Windowed attention: grid (1024 windows, 4 head-groups), 4 heads per CTA
// ---------------------------------------------------------------------------
__global__ __launch_bounds__(256) void attn_kernel(const float* __restrict__ q,
                                                   const float* __restrict__ kv,
                                                   const float* __restrict__ rb,
                                                   float* __restrict__ out) {
    __shared__ __align__(16) float sq [64][36];
    __shared__ __align__(16) float skT[32][68];
    __shared__ __align__(16) float sv [64][36];
    __shared__ float sc[64][65];

    const int tid = threadIdx.x;
    const int win = blockIdx.x;
    const int wi  = win & 63;
    const int wr  = wi >> 3, wc = wi & 7;
    const int base = win << 6;
    const int h0  = blockIdx.y << 2;

    for (int h = h0; h < h0 + 4; h++) {
        for (int i = tid; i < 2048; i += 256) {
            int n = i >> 5, d = i & 31;
            sq[n][d] = q [(size_t)(base + n) * 512  + h * 32 + d];
            skT[d][n]= kv[(size_t)(base + n) * 1024 + h * 32 + d];
            sv[n][d] = kv[(size_t)(base + n) * 1024 + 512 + h * 32 + d];
        }
        __syncthreads();

        const int tn = (tid >> 4) << 2;
        const int tm = (tid & 15) << 2;
        float rs[4][4] = {};
        for (int dc = 0; dc < 32; dc += 4) {
            float a[4][4], bb[4][4];
#pragma unroll
            for (int i = 0; i < 4; i++)
                *(float4*)a[i] = *(const float4*)&sq[tn + i][dc];
#pragma unroll
            for (int l = 0; l < 4; l++)
                *(float4*)bb[l] = *(const float4*)&skT[dc + l][tm];
#pragma unroll
            for (int i = 0; i < 4; i++)
#pragma unroll
                for (int j = 0; j < 4; j++)
#pragma unroll
                    for (int l = 0; l < 4; l++)
                        rs[i][j] += a[i][l] * bb[l][j];
        }
#pragma unroll
        for (int i = 0; i < 4; i++) {
            int n = tn + i;
            int cn = 15 * (n >> 3) + (n & 7);
            int rhn = (wr == 7) ? (((n >> 3) < 4) ? 1 : 2) : 0;
            int rwn = (wc == 7) ? (((n & 7)  < 4) ? 1 : 2) : 0;
            int regn = rhn * 3 + rwn;
#pragma unroll
            for (int j = 0; j < 4; j++) {
                int m = tm + j;
                int m2 = 63 - m;
                int cm = 15 * (m2 >> 3) + (m2 & 7);
                float bv = rb[(cn + cm) * 16 + h];
                int rhm = (wr == 7) ? (((m >> 3) < 4) ? 1 : 2) : 0;
                int rwm = (wc == 7) ? (((m & 7)  < 4) ? 1 : 2) : 0;
                float msk = ((rhm * 3 + rwm) != regn) ? -100.f : 0.f;
                sc[n][m] = rs[i][j] + bv + msk;
            }
        }
        __syncthreads();

        {
            int row = tid >> 2, sub = tid & 3;
            float mx = -1e30f;
#pragma unroll
            for (int j = 0; j < 16; j++) mx = fmaxf(mx, sc[row][sub + 4 * j]);
            mx = fmaxf(mx, __shfl_xor_sync(0xffffffffu, mx, 1));
            mx = fmaxf(mx, __shfl_xor_sync(0xffffffffu, mx, 2));
            float ev[16], sm = 0.f;
#pragma unroll
            for (int j = 0; j < 16; j++) {
                ev[j] = expf(sc[row][sub + 4 * j] - mx);
                sm += ev[j];
            }
            sm += __shfl_xor_sync(0xffffffffu, sm, 1);
            sm += __shfl_xor_sync(0xffffffffu, sm, 2);
            float inv = 1.f / sm;
#pragma unroll
            for (int j = 0; j < 16; j++) sc[row][sub + 4 * j] = ev[j] * inv;
        }
        __syncthreads();

        {
            int n0 = (tid >> 3) << 1;
            int d0 = (tid & 7) << 2;
            float o0[4] = {}, o1[4] = {};
            for (int m = 0; m < 64; m++) {
                float4 vv = *(const float4*)&sv[m][d0];
                float s0 = sc[n0][m], s1 = sc[n0 + 1][m];
                o0[0] += s0 * vv.x; o0[1] += s0 * vv.y; o0[2] += s0 * vv.z; o0[3] += s0 * vv.w;
                o1[0] += s1 * vv.x; o1[1] += s1 * vv.y; o1[2] += s1 * vv.z; o1[3] += s1 * vv.w;
            }
            *(float4*)&out[(size_t)(base + n0)     * 512 + h * 32 + d0] =
                make_float4(o0[0], o0[1], o0[2], o0[3]);
            *(float4*)&out[(size_t)(base + n0 + 1) * 512 + h * 32 + d0] =
                make_float4(o1[0], o1[1], o1[2], o1[3]);
        }
        __syncthreads();
    }
}

// ---------------------------------------------------------------------------
extern "C" void kernel_launch(void* const* d_in, const int* in_sizes, int n_in,
                              void* d_out, int out_size) {
    const float* x      = (const float*)d_in[0];
    const float* skip   = (const float*)d_in[1];
    const float* n1g    = (const float*)d_in[2];
    const float* n1b    = (const float*)d_in[3];
    const float* w_qkv  = (const float*)d_in[4];
    const float* b_qkv  = (const float*)d_in[5];
    const float* w_skip = (const float*)d_in[6];
    const float* b_skip = (const float*)d_in[7];
    const float* relb   = (const float*)d_in[8];
    const float* w_proj = (const float*)d_in[9];
    const float* b_proj = (const float*)d_in[10];
    const float* n2g    = (const float*)d_in[11];
    const float* n2b    = (const float*)d_in[12];
    const float* w_fc1  = (const float*)d_in[13];
    const float* b_fc1  = (const float*)d_in[14];
    const float* w_fc2  = (const float*)d_in[15];
    const float* b_fc2  = (const float*)d_in[16];
    float* outp = (float*)d_out;

    float *lnx, *lnskip, *kvb, *qb, *xres, *hb;
    cudaGetSymbolAddress((void**)&lnx,    g_lnx);
    cudaGetSymbolAddress((void**)&lnskip, g_lnskip);
    cudaGetSymbolAddress((void**)&kvb,    g_kv);
    cudaGetSymbolAddress((void**)&qb,     g_q);
    cudaGetSymbolAddress((void**)&xres,   g_xres);
    cudaGetSymbolAddress((void**)&hb,     g_h);

    cudaFuncSetAttribute(gemm_tf32<0>, cudaFuncAttributeMaxDynamicSharedMemorySize, GEMM_SMEM_BYTES);
    cudaFuncSetAttribute(gemm_tf32<1>, cudaFuncAttributeMaxDynamicSharedMemorySize, GEMM_SMEM_BYTES);
    cudaFuncSetAttribute(gemm_tf32<2>, cudaFuncAttributeMaxDynamicSharedMemorySize, GEMM_SMEM_BYTES);
    cudaFuncSetAttribute(gemm_tf32<3>, cudaFuncAttributeMaxDynamicSharedMemorySize, GEMM_SMEM_BYTES);
    cudaFuncSetAttribute(gemm_tf32<4>, cudaFuncAttributeMaxDynamicSharedMemorySize, GEMM_SMEM_BYTES);

    ln1_kernel<<<8192, 256>>>(x, skip, n1g, n1b, lnx, lnskip);
    gemm_tf32<0><<<dim3(8, 512), 256, GEMM_SMEM_BYTES>>>(lnx, w_qkv, b_qkv, kvb, nullptr, TOK, 1024, 512);
    gemm_tf32<1><<<dim3(4, 512), 256, GEMM_SMEM_BYTES>>>(lnskip, w_skip, b_skip, qb, nullptr, TOK, 512, 512);
    attn_kernel<<<dim3(1024, 4), 256>>>(qb, kvb, relb, lnskip);
    gemm_tf32<2><<<dim3(4, 512), 256, GEMM_SMEM_BYTES>>>(lnskip, w_proj, b_proj, xres, x, TOK, 512, 512);
    ln2_kernel<<<8192, 256>>>(xres, n2g, n2b, lnx);
    gemm_tf32<3><<<dim3(16, 512), 256, GEMM_SMEM_BYTES>>>(lnx, w_fc1, b_fc1, hb, nullptr, TOK, FFN, 512);
    gemm_tf32<4><<<dim3(4, 512), 256, GEMM_SMEM_BYTES>>>(hb, w_fc2, b_fc2, outp, xres, TOK, 512, FFN);
    (void)in_sizes; (void)n_in; (void)out_size;
}

// round 7
// speedup vs baseline: 1.5851x; 1.1354x over previous
#include <cuda_runtime.h>
#include <cstdint>

// ---------------------------------------------------------------------------
// SwinBlock sm_103a round 6: fragment-order tf32 mma.sync GEMMs.
// Fix vs round 5: EPI3 (gelu->A-layout) tile stride uses output N, not K.
// ---------------------------------------------------------------------------

#define TOK   65536
#define CEMB  512
#define FFN   2048

__device__ float g_axA [(size_t)TOK * CEMB];
__device__ float g_asA [(size_t)TOK * CEMB];
__device__ float g_kv  [(size_t)TOK * 1024];
__device__ float g_q   [(size_t)TOK * CEMB];
__device__ float g_xres[(size_t)TOK * CEMB];
__device__ float g_hA  [(size_t)TOK * FFN];
__device__ float g_wqkvB[1024 * 512];
__device__ float g_wskipB[512 * 512];
__device__ float g_wprojB[512 * 512];
__device__ float g_wfc1B[2048 * 512];
__device__ float g_wfc2B[512 * 2048];

__device__ __forceinline__ int wt_to_nat(int wt) {
    int n   = wt & 63;
    int win = wt >> 6;
    int wi  = win & 63;
    int b   = win >> 6;
    int hp  = ((wi >> 3) << 3) + (n >> 3);
    int wp  = ((wi & 7)  << 3) + (n & 7);
    int h   = (hp + 4) & 63;
    int w   = (wp + 4) & 63;
    return (b << 12) + (h << 6) + w;
}

__device__ __forceinline__ float tf32r(float x) {
    uint32_t u;
    asm("cvt.rna.tf32.f32 %0, %1;" : "=r"(u) : "f"(x));
    return __uint_as_float(u);
}

__device__ __forceinline__ void mma8(float c[4], const float4& a, float b0, float b1) {
    asm volatile(
        "mma.sync.aligned.m16n8k8.row.col.f32.tf32.tf32.f32 "
        "{%0,%1,%2,%3}, {%4,%5,%6,%7}, {%8,%9}, {%0,%1,%2,%3};\n"
        : "+f"(c[0]), "+f"(c[1]), "+f"(c[2]), "+f"(c[3])
        : "r"(__float_as_uint(a.x)), "r"(__float_as_uint(a.y)),
          "r"(__float_as_uint(a.z)), "r"(__float_as_uint(a.w)),
          "r"(__float_as_uint(b0)),  "r"(__float_as_uint(b1)));
}

__device__ __forceinline__ void cpa16(uint32_t dst, const void* src) {
    asm volatile("cp.async.cg.shared.global [%0], [%1], 16;\n" :: "r"(dst), "l"(src));
}
__device__ __forceinline__ void cpa_commit() { asm volatile("cp.async.commit_group;\n"); }
__device__ __forceinline__ void cpa_wait1()  { asm volatile("cp.async.wait_group 1;\n"); }
__device__ __forceinline__ void cpa_wait0()  { asm volatile("cp.async.wait_group 0;\n"); }

// ---------------------------------------------------------------------------
// LayerNorm -> staged tf32 A-layout. 512 threads = 16 warps = 16-row group.
// ---------------------------------------------------------------------------
__device__ __forceinline__ void ln_row_st(const float* __restrict__ in,
                                          const float* __restrict__ g,
                                          const float* __restrict__ b,
                                          float* __restrict__ stgrow, int lane) {
    float4 v[4];
    float s = 0.f, sq = 0.f;
#pragma unroll
    for (int j = 0; j < 4; j++) {
        v[j] = *(const float4*)(in + (((j << 5) + lane) << 2));
        s  += v[j].x + v[j].y + v[j].z + v[j].w;
        sq += v[j].x*v[j].x + v[j].y*v[j].y + v[j].z*v[j].z + v[j].w*v[j].w;
    }
#pragma unroll
    for (int o = 16; o; o >>= 1) {
        s  += __shfl_xor_sync(0xffffffffu, s, o);
        sq += __shfl_xor_sync(0xffffffffu, sq, o);
    }
    float mean = s * (1.f / 512.f);
    float var  = sq * (1.f / 512.f) - mean * mean;
    float rstd = rsqrtf(var + 1e-5f);
#pragma unroll
    for (int j = 0; j < 4; j++) {
        int off = (((j << 5) + lane) << 2);
        float4 gg = *(const float4*)(g + off);
        float4 bb = *(const float4*)(b + off);
        stgrow[off + 0] = tf32r((v[j].x - mean) * rstd * gg.x + bb.x);
        stgrow[off + 1] = tf32r((v[j].y - mean) * rstd * gg.y + bb.y);
        stgrow[off + 2] = tf32r((v[j].z - mean) * rstd * gg.z + bb.z);
        stgrow[off + 3] = tf32r((v[j].w - mean) * rstd * gg.w + bb.w);
    }
}

__device__ __forceinline__ void stg_writeA(float* __restrict__ out, int row0,
                                           const float (*stg)[516]) {
    size_t base = (size_t)(row0 >> 7) * (128 * 512) + (size_t)((row0 >> 4) & 7) * 128;
#pragma unroll
    for (int i = 0; i < 4; i++) {
        int f4 = threadIdx.x + (i << 9);
        int kb8 = f4 >> 5;
        int p   = (f4 & 31) << 2;
        int lr  = (p >> 2) >> 2;
        int kc  = (p >> 2) & 3;
        int k0  = (kb8 << 3) + kc;
        float4 o;
        o.x = stg[lr    ][k0    ];
        o.y = stg[lr + 8][k0    ];
        o.z = stg[lr    ][k0 + 4];
        o.w = stg[lr + 8][k0 + 4];
        *(float4*)(out + base + (size_t)kb8 * 1024 + p) = o;
    }
}

__global__ __launch_bounds__(512) void ln1_kernel(const float* __restrict__ x,
                                                  const float* __restrict__ skip,
                                                  const float* __restrict__ g1,
                                                  const float* __restrict__ b1,
                                                  float* __restrict__ outxA,
                                                  float* __restrict__ outsA) {
    __shared__ float stg[16][516];
    int warp = threadIdx.x >> 5, lane = threadIdx.x & 31;
    int row0 = blockIdx.x << 4;
    int nat  = wt_to_nat(row0 + warp);
    ln_row_st(x + (size_t)nat * CEMB, g1, b1, stg[warp], lane);
    __syncthreads();
    stg_writeA(outxA, row0, stg);
    __syncthreads();
    ln_row_st(skip + (size_t)nat * CEMB, g1, b1, stg[warp], lane);
    __syncthreads();
    stg_writeA(outsA, row0, stg);
}

__global__ __launch_bounds__(512) void ln2_kernel(const float* __restrict__ xin,
                                                  const float* __restrict__ g2,
                                                  const float* __restrict__ b2,
                                                  float* __restrict__ outA) {
    __shared__ float stg[16][516];
    int warp = threadIdx.x >> 5, lane = threadIdx.x & 31;
    int row0 = blockIdx.x << 4;
    ln_row_st(xin + (size_t)(row0 + warp) * CEMB, g2, b2, stg[warp], lane);
    __syncthreads();
    stg_writeA(outA, row0, stg);
}

// weight f32 natural [N][K] -> B-layout tf32
__global__ __launch_bounds__(256) void wconvB_kernel(const float* __restrict__ w,
                                                     float* __restrict__ out,
                                                     int K, int n4) {
    int id = blockIdx.x * 256 + threadIdx.x;
    if (id >= n4) return;
    int p0   = id << 2;
    int tp   = K << 7;
    int tile = p0 / tp;
    int rem  = p0 - tile * tp;
    int kb8  = rem >> 10;
    int rp   = rem & 1023;
    int grp  = rp >> 7;
    int p    = rp & 127;
    int lane = p >> 2;
    int nb   = (tile << 7) + (grp << 4) + (lane >> 2);
    int kb   = (kb8 << 3) + (lane & 3);
    float4 o;
    o.x = tf32r(w[(size_t)nb * K + kb]);
    o.y = tf32r(w[(size_t)nb * K + kb + 4]);
    o.z = tf32r(w[(size_t)(nb + 8) * K + kb]);
    o.w = tf32r(w[(size_t)(nb + 8) * K + kb + 4]);
    *(float4*)(out + p0) = o;
}

// ---------------------------------------------------------------------------
// GEMM: CTA 256x128, 8 warps (4m x 2n), warp 64x64, BK=32, 2-stage cp.async.
// EPI: 0 +bias | 1 (+bias)*scale | 2 +res scatter nat | 3 gelu->A-layout | 4 +res
// ---------------------------------------------------------------------------
#define STG_BYTES 49152
#define GEMM_SMEM (2 * STG_BYTES)

template <int EPI>
__global__ __launch_bounds__(256) void gemm_frag(const float* __restrict__ A,
                                                 const float* __restrict__ W,
                                                 const float* __restrict__ bias,
                                                 float* __restrict__ out,
                                                 const float* __restrict__ res,
                                                 int N, int K) {
    extern __shared__ __align__(16) char smem[];
    const uint32_t sb = (uint32_t)__cvta_generic_to_shared(smem);
    const int tid  = threadIdx.x;
    const int warp = tid >> 5, lane = tid & 31;
    const int wm4  = warp >> 1;
    const int wn   = warp & 1;
    const int g    = lane >> 2, tq = lane & 3;
    const int bm   = blockIdx.y * 256;
    const int bn   = blockIdx.x * 128;

    const size_t aTile = (size_t)(bm >> 7) * 128 * K;
    const size_t bTile = (size_t)(bn >> 7) * 128 * K;

    float acc[4][8][4];
#pragma unroll
    for (int i = 0; i < 4; i++)
#pragma unroll
        for (int j = 0; j < 8; j++)
#pragma unroll
            for (int l = 0; l < 4; l++) acc[i][j][l] = 0.f;

    auto load_stage = [&](int s, int kb) {
        const uint32_t dst = sb + (uint32_t)s * STG_BYTES;
        const size_t ko = (size_t)kb * 4096;
#pragma unroll
        for (int j = 0; j < 8; j++) {
            int f4 = tid + (j << 8);
            int tile = f4 >> 10;
            int rem  = f4 & 1023;
            cpa16(dst + (uint32_t)f4 * 16,
                  A + aTile + (size_t)tile * 128 * K + ko + (rem << 2));
        }
#pragma unroll
        for (int j = 0; j < 4; j++) {
            int f4 = tid + (j << 8);
            cpa16(dst + 32768 + (uint32_t)f4 * 16, W + bTile + ko + (f4 << 2));
        }
    };

    const int nkb = K >> 5;
    load_stage(0, 0); cpa_commit();
    load_stage(1, 1); cpa_commit();

    for (int kb = 0; kb < nkb; kb++) {
        cpa_wait1();
        __syncthreads();
        const float4* As4 = (const float4*)(smem + (size_t)(kb & 1) * STG_BYTES);
        const float4* Bs4 = (const float4*)(smem + (size_t)(kb & 1) * STG_BYTES + 32768);
        const int aw = ((wm4 >> 1) << 10) + (((wm4 & 1) << 2) << 5);
        const int bw = ((wn << 2) << 5);
#pragma unroll
        for (int kb8 = 0; kb8 < 4; kb8++) {
            float4 a[4], b[4];
#pragma unroll
            for (int mi = 0; mi < 4; mi++)
                a[mi] = As4[aw + (kb8 << 8) + (mi << 5) + lane];
#pragma unroll
            for (int nj = 0; nj < 4; nj++)
                b[nj] = Bs4[bw + (kb8 << 8) + (nj << 5) + lane];
#pragma unroll
            for (int mi = 0; mi < 4; mi++)
#pragma unroll
                for (int nj = 0; nj < 4; nj++) {
                    mma8(acc[mi][2 * nj],     a[mi], b[nj].x, b[nj].y);
                    mma8(acc[mi][2 * nj + 1], a[mi], b[nj].z, b[nj].w);
                }
        }
        __syncthreads();
        if (kb + 2 < nkb) load_stage(kb & 1, kb + 2);
        cpa_commit();
    }

    if (EPI == 3) {
        // gelu -> A-layout (fc2's A input). FIX: tile stride uses N (output dim).
        cpa_wait0();
        __syncthreads();
        float* stg = (float*)smem;   // [128][132]
#pragma unroll
        for (int half = 0; half < 2; half++) {
            if ((wm4 >> 1) == half) {
                const int lrb = (wm4 & 1) * 64;
#pragma unroll
                for (int mi = 0; mi < 4; mi++)
#pragma unroll
                    for (int n8 = 0; n8 < 8; n8++) {
                        int lc = wn * 64 + n8 * 8 + (tq << 1);
                        float bv0 = bias[bn + lc], bv1 = bias[bn + lc + 1];
#pragma unroll
                        for (int hr = 0; hr < 2; hr++) {
                            int lr = lrb + mi * 16 + g + hr * 8;
                            float v0 = acc[mi][n8][hr * 2]     + bv0;
                            float v1 = acc[mi][n8][hr * 2 + 1] + bv1;
                            const float is2 = 0.70710678118654752f;
                            stg[lr * 132 + lc]     = tf32r(0.5f * v0 * (1.f + erff(v0 * is2)));
                            stg[lr * 132 + lc + 1] = tf32r(0.5f * v1 * (1.f + erff(v1 * is2)));
                        }
                    }
            }
            __syncthreads();
            size_t tbase = (size_t)((bm >> 7) + half) * 128 * N + (size_t)(bn >> 3) * 1024;
#pragma unroll
            for (int i = 0; i < 16; i++) {
                int f4 = tid + (i << 8);
                int block = f4 >> 5;
                int kb8L = block >> 3;
                int grp  = block & 7;
                int p    = (f4 & 31) << 2;
                int lr   = (grp << 4) + ((p >> 2) >> 2);
                int k0   = (kb8L << 3) + ((p >> 2) & 3);
                float4 o;
                o.x = stg[lr * 132 + k0];
                o.y = stg[(lr + 8) * 132 + k0];
                o.z = stg[lr * 132 + k0 + 4];
                o.w = stg[(lr + 8) * 132 + k0 + 4];
                *(float4*)(out + tbase + (size_t)kb8L * 1024 + (size_t)grp * 128 + p) = o;
            }
            __syncthreads();
        }
        return;
    }

#pragma unroll
    for (int mi = 0; mi < 4; mi++) {
#pragma unroll
        for (int hr = 0; hr < 2; hr++) {
            int r = bm + wm4 * 64 + mi * 16 + g + hr * 8;
            size_t obase;
            if (EPI == 2) obase = (size_t)wt_to_nat(r) * CEMB;
            else          obase = (size_t)r * N;
#pragma unroll
            for (int n8 = 0; n8 < 8; n8++) {
                int c = bn + wn * 64 + n8 * 8 + (tq << 1);
                float v0 = acc[mi][n8][hr * 2]     + bias[c];
                float v1 = acc[mi][n8][hr * 2 + 1] + bias[c + 1];
                if (EPI == 1) {
                    const float sc = 0.17677669529663687f;
                    v0 *= sc; v1 *= sc;
                } else if (EPI == 2 || EPI == 4) {
                    v0 += res[obase + c];
                    v1 += res[obase + c + 1];
                }
                *(float2*)(out + obase + c) = make_float2(v0, v1);
            }
        }
    }
}

// ---------------------------------------------------------------------------
// Windowed attention (fp32). Output staged -> tf32 A-layout.
// ---------------------------------------------------------------------------
__global__ __launch_bounds__(256) void attn_kernel(const float* __restrict__ q,
                                                   const float* __restrict__ kv,
                                                   const float* __restrict__ rb,
                                                   float* __restrict__ outA) {
    __shared__ __align__(16) float sq [64][36];
    __shared__ __align__(16) float skT[32][68];
    __shared__ __align__(16) float sv [64][36];
    __shared__ float sc[64][65];
    __shared__ float so[64][33];

    const int tid = threadIdx.x;
    const int win = blockIdx.x;
    const int wi  = win & 63;
    const int wr  = wi >> 3, wc = wi & 7;
    const int base = win << 6;
    const int h0  = blockIdx.y << 2;
    const size_t tbase = (size_t)(win >> 1) * (128 * 512) + (size_t)((win & 1) * 4) * 128;

    for (int h = h0; h < h0 + 4; h++) {
        for (int i = tid; i < 2048; i += 256) {
            int n = i >> 5, d = i & 31;
            sq[n][d] = q [(size_t)(base + n) * 512  + h * 32 + d];
            skT[d][n]= kv[(size_t)(base + n) * 1024 + h * 32 + d];
            sv[n][d] = kv[(size_t)(base + n) * 1024 + 512 + h * 32 + d];
        }
        __syncthreads();

        const int tn = (tid >> 4) << 2;
        const int tm = (tid & 15) << 2;
        float rs[4][4] = {};
        for (int dc = 0; dc < 32; dc += 4) {
            float a[4][4], bb[4][4];
#pragma unroll
            for (int i = 0; i < 4; i++)
                *(float4*)a[i] = *(const float4*)&sq[tn + i][dc];
#pragma unroll
            for (int l = 0; l < 4; l++)
                *(float4*)bb[l] = *(const float4*)&skT[dc + l][tm];
#pragma unroll
            for (int i = 0; i < 4; i++)
#pragma unroll
                for (int j = 0; j < 4; j++)
#pragma unroll
                    for (int l = 0; l < 4; l++)
                        rs[i][j] += a[i][l] * bb[l][j];
        }
#pragma unroll
        for (int i = 0; i < 4; i++) {
            int n = tn + i;
            int cn = 15 * (n >> 3) + (n & 7);
            int rhn = (wr == 7) ? (((n >> 3) < 4) ? 1 : 2) : 0;
            int rwn = (wc == 7) ? (((n & 7)  < 4) ? 1 : 2) : 0;
            int regn = rhn * 3 + rwn;
#pragma unroll
            for (int j = 0; j < 4; j++) {
                int m = tm + j;
                int m2 = 63 - m;
                int cm = 15 * (m2 >> 3) + (m2 & 7);
                float bv = rb[(cn + cm) * 16 + h];
                int rhm = (wr == 7) ? (((m >> 3) < 4) ? 1 : 2) : 0;
                int rwm = (wc == 7) ? (((m & 7)  < 4) ? 1 : 2) : 0;
                float msk = ((rhm * 3 + rwm) != regn) ? -100.f : 0.f;
                sc[n][m] = rs[i][j] + bv + msk;
            }
        }
        __syncthreads();

        {
            int row = tid >> 2, sub = tid & 3;
            float mx = -1e30f;
#pragma unroll
            for (int j = 0; j < 16; j++) mx = fmaxf(mx, sc[row][sub + 4 * j]);
            mx = fmaxf(mx, __shfl_xor_sync(0xffffffffu, mx, 1));
            mx = fmaxf(mx, __shfl_xor_sync(0xffffffffu, mx, 2));
            float ev[16], sm = 0.f;
#pragma unroll
            for (int j = 0; j < 16; j++) {
                ev[j] = expf(sc[row][sub + 4 * j] - mx);
                sm += ev[j];
            }
            sm += __shfl_xor_sync(0xffffffffu, sm, 1);
            sm += __shfl_xor_sync(0xffffffffu, sm, 2);
            float inv = 1.f / sm;
#pragma unroll
            for (int j = 0; j < 16; j++) sc[row][sub + 4 * j] = ev[j] * inv;
        }
        __syncthreads();

        {
            int n0 = (tid >> 3) << 1;
            int d0 = (tid & 7) << 2;
            float o0[4] = {}, o1[4] = {};
            for (int m = 0; m < 64; m++) {
                float4 vv = *(const float4*)&sv[m][d0];
                float s0 = sc[n0][m], s1 = sc[n0 + 1][m];
                o0[0] += s0 * vv.x; o0[1] += s0 * vv.y; o0[2] += s0 * vv.z; o0[3] += s0 * vv.w;
                o1[0] += s1 * vv.x; o1[1] += s1 * vv.y; o1[2] += s1 * vv.z; o1[3] += s1 * vv.w;
            }
#pragma unroll
            for (int l = 0; l < 4; l++) {
                so[n0][d0 + l]     = tf32r(o0[l]);
                so[n0 + 1][d0 + l] = tf32r(o1[l]);
            }
        }
        __syncthreads();

#pragma unroll
        for (int i = 0; i < 2; i++) {
            int f4 = tid + (i << 8);
            int block = f4 >> 5;
            int grpL = block >> 2;
            int kb8L = block & 3;
            int p    = (f4 & 31) << 2;
            int lr   = (grpL << 4) + ((p >> 2) >> 2);
            int k0   = (kb8L << 3) + ((p >> 2) & 3);
            float4 o;
            o.x = so[lr][k0];
            o.y = so[lr + 8][k0];
            o.z = so[lr][k0 + 4];
            o.w = so[lr + 8][k0 + 4];
            *(float4*)(outA + tbase + (size_t)(4 * h + kb8L) * 1024 + grpL * 128 + p) = o;
        }
        __syncthreads();
    }
}

// ---------------------------------------------------------------------------
extern "C" void kernel_launch(void* const* d_in, const int* in_sizes, int n_in,
                              void* d_out, int out_size) {
    const float* x      = (const float*)d_in[0];
    const float* skip   = (const float*)d_in[1];
    const float* n1g    = (const float*)d_in[2];
    const float* n1b    = (const float*)d_in[3];
    const float* w_qkv  = (const float*)d_in[4];
    const float* b_qkv  = (const float*)d_in[5];
    const float* w_skip = (const float*)d_in[6];
    const float* b_skip = (const float*)d_in[7];
    const float* relb   = (const float*)d_in[8];
    const float* w_proj = (const float*)d_in[9];
    const float* b_proj = (const float*)d_in[10];
    const float* n2g    = (const float*)d_in[11];
    const float* n2b    = (const float*)d_in[12];
    const float* w_fc1  = (const float*)d_in[13];
    const float* b_fc1  = (const float*)d_in[14];
    const float* w_fc2  = (const float*)d_in[15];
    const float* b_fc2  = (const float*)d_in[16];
    float* outp = (float*)d_out;

    float *axA, *asA, *kvb, *qb, *xres, *hA;
    float *wqB, *wsB, *wpB, *w1B, *w2B;
    cudaGetSymbolAddress((void**)&axA, g_axA);
    cudaGetSymbolAddress((void**)&asA, g_asA);
    cudaGetSymbolAddress((void**)&kvb, g_kv);
    cudaGetSymbolAddress((void**)&qb,  g_q);
    cudaGetSymbolAddress((void**)&xres, g_xres);
    cudaGetSymbolAddress((void**)&hA,  g_hA);
    cudaGetSymbolAddress((void**)&wqB, g_wqkvB);
    cudaGetSymbolAddress((void**)&wsB, g_wskipB);
    cudaGetSymbolAddress((void**)&wpB, g_wprojB);
    cudaGetSymbolAddress((void**)&w1B, g_wfc1B);
    cudaGetSymbolAddress((void**)&w2B, g_wfc2B);

    cudaFuncSetAttribute(gemm_frag<0>, cudaFuncAttributeMaxDynamicSharedMemorySize, GEMM_SMEM);
    cudaFuncSetAttribute(gemm_frag<1>, cudaFuncAttributeMaxDynamicSharedMemorySize, GEMM_SMEM);
    cudaFuncSetAttribute(gemm_frag<2>, cudaFuncAttributeMaxDynamicSharedMemorySize, GEMM_SMEM);
    cudaFuncSetAttribute(gemm_frag<3>, cudaFuncAttributeMaxDynamicSharedMemorySize, GEMM_SMEM);
    cudaFuncSetAttribute(gemm_frag<4>, cudaFuncAttributeMaxDynamicSharedMemorySize, GEMM_SMEM);

    wconvB_kernel<<<(1024*512/4 + 255)/256, 256>>>(w_qkv,  wqB, 512,  1024*512/4);
    wconvB_kernel<<<(512*512/4  + 255)/256, 256>>>(w_skip, wsB, 512,  512*512/4);
    wconvB_kernel<<<(512*512/4  + 255)/256, 256>>>(w_proj, wpB, 512,  512*512/4);
    wconvB_kernel<<<(2048*512/4 + 255)/256, 256>>>(w_fc1,  w1B, 512,  2048*512/4);
    wconvB_kernel<<<(512*2048/4 + 255)/256, 256>>>(w_fc2,  w2B, 2048, 512*2048/4);

    ln1_kernel<<<4096, 512>>>(x, skip, n1g, n1b, axA, asA);
    gemm_frag<0><<<dim3(8, 256), 256, GEMM_SMEM>>>(axA, wqB, b_qkv, kvb, nullptr, 1024, 512);
    gemm_frag<1><<<dim3(4, 256), 256, GEMM_SMEM>>>(asA, wsB, b_skip, qb, nullptr, 512, 512);
    attn_kernel<<<dim3(1024, 4), 256>>>(qb, kvb, relb, asA);
    gemm_frag<2><<<dim3(4, 256), 256, GEMM_SMEM>>>(asA, wpB, b_proj, xres, x, 512, 512);
    ln2_kernel<<<4096, 512>>>(xres, n2g, n2b, axA);
    gemm_frag<3><<<dim3(16, 256), 256, GEMM_SMEM>>>(axA, w1B, b_fc1, hA, nullptr, 2048, 512);
    gemm_frag<4><<<dim3(4, 256), 256, GEMM_SMEM>>>(hA, w2B, b_fc2, outp, xres, 512, 2048);
    (void)in_sizes; (void)n_in; (void)out_size;
}

// round 8
// speedup vs baseline: 2.3853x; 1.5048x over previous
#include <cuda_runtime.h>
#include <cuda_fp16.h>
#include <cstdint>

// ---------------------------------------------------------------------------
// SwinBlock sm_103a round 7: fp16 m16n8k16 mma.sync (same 10-bit mantissa as
// tf32 => same accuracy, 2x K per instruction, half the bytes).
//  - A/B stored in m16n8k16 fragment order in gmem (fp16), producers emit it.
//  - CTA 256x128, warp 64x64, BK=64, 2-stage cp.async, 96KB smem.
// Fragment maps (lane = g*4+tq, g=lane>>2, tq=lane&3):
//  A 16x16 blk, lane's 8 halves: (g,2tq)(g,2tq+1)(g+8,2tq)(g+8,2tq+1)
//                                (g,2tq+8)(g,2tq+9)(g+8,2tq+8)(g+8,2tq+9)
//  B 16k x 16n blk, lane's 8 halves: (2tq,g)(2tq+1,g)(2tq+8,g)(2tq+9,g)
//                                    then same with n=g+8
//  Block = 32 lanes * 16B = 512B; A tile: kb16-major then rowgrp; halves off =
//    tile*128*K + kb16*2048 + grp*256 + lane*8
// ---------------------------------------------------------------------------

#define TOK   65536
#define CEMB  512
#define FFN   2048

__device__ __half g_axA [(size_t)TOK * CEMB];
__device__ __half g_asA [(size_t)TOK * CEMB];
__device__ float  g_kv  [(size_t)TOK * 1024];
__device__ float  g_q   [(size_t)TOK * CEMB];
__device__ float  g_xres[(size_t)TOK * CEMB];
__device__ __half g_hA  [(size_t)TOK * FFN];
__device__ __half g_wqkvB[1024 * 512];
__device__ __half g_wskipB[512 * 512];
__device__ __half g_wprojB[512 * 512];
__device__ __half g_wfc1B[2048 * 512];
__device__ __half g_wfc2B[512 * 2048];

__device__ __forceinline__ int wt_to_nat(int wt) {
    int n   = wt & 63;
    int win = wt >> 6;
    int wi  = win & 63;
    int b   = win >> 6;
    int hp  = ((wi >> 3) << 3) + (n >> 3);
    int wp  = ((wi & 7)  << 3) + (n & 7);
    int h   = (hp + 4) & 63;
    int w   = (wp + 4) & 63;
    return (b << 12) + (h << 6) + w;
}

__device__ __forceinline__ uint32_t pk2(float a, float b) {
    __half2 h = __floats2half2_rn(a, b);
    return *(uint32_t*)&h;
}

__device__ __forceinline__ void mma16(float c[4], const uint32_t a[4],
                                      uint32_t b0, uint32_t b1) {
    asm volatile(
        "mma.sync.aligned.m16n8k16.row.col.f32.f16.f16.f32 "
        "{%0,%1,%2,%3}, {%4,%5,%6,%7}, {%8,%9}, {%0,%1,%2,%3};\n"
        : "+f"(c[0]), "+f"(c[1]), "+f"(c[2]), "+f"(c[3])
        : "r"(a[0]), "r"(a[1]), "r"(a[2]), "r"(a[3]), "r"(b0), "r"(b1));
}

__device__ __forceinline__ void cpa16(uint32_t dst, const void* src) {
    asm volatile("cp.async.cg.shared.global [%0], [%1], 16;\n" :: "r"(dst), "l"(src));
}
__device__ __forceinline__ void cpa_commit() { asm volatile("cp.async.commit_group;\n"); }
__device__ __forceinline__ void cpa_wait1()  { asm volatile("cp.async.wait_group 1;\n"); }
__device__ __forceinline__ void cpa_wait0()  { asm volatile("cp.async.wait_group 0;\n"); }

// ---------------------------------------------------------------------------
// LayerNorm -> f32 smem staging -> fp16 A-layout write.
// ---------------------------------------------------------------------------
__device__ __forceinline__ void ln_row_st(const float* __restrict__ in,
                                          const float* __restrict__ g,
                                          const float* __restrict__ b,
                                          float* __restrict__ stgrow, int lane) {
    float4 v[4];
    float s = 0.f, sq = 0.f;
#pragma unroll
    for (int j = 0; j < 4; j++) {
        v[j] = *(const float4*)(in + (((j << 5) + lane) << 2));
        s  += v[j].x + v[j].y + v[j].z + v[j].w;
        sq += v[j].x*v[j].x + v[j].y*v[j].y + v[j].z*v[j].z + v[j].w*v[j].w;
    }
#pragma unroll
    for (int o = 16; o; o >>= 1) {
        s  += __shfl_xor_sync(0xffffffffu, s, o);
        sq += __shfl_xor_sync(0xffffffffu, sq, o);
    }
    float mean = s * (1.f / 512.f);
    float var  = sq * (1.f / 512.f) - mean * mean;
    float rstd = rsqrtf(var + 1e-5f);
#pragma unroll
    for (int j = 0; j < 4; j++) {
        int off = (((j << 5) + lane) << 2);
        float4 gg = *(const float4*)(g + off);
        float4 bb = *(const float4*)(b + off);
        stgrow[off + 0] = (v[j].x - mean) * rstd * gg.x + bb.x;
        stgrow[off + 1] = (v[j].y - mean) * rstd * gg.y + bb.y;
        stgrow[off + 2] = (v[j].z - mean) * rstd * gg.z + bb.z;
        stgrow[off + 3] = (v[j].w - mean) * rstd * gg.w + bb.w;
    }
}

// write 16 rows (one rowgrp) of A-layout from stg[16][516]
__device__ __forceinline__ void stg_writeA16(__half* __restrict__ out, int row0,
                                             const float (*stg)[516]) {
    size_t base = (size_t)(row0 >> 7) * (128 * 512) + (size_t)((row0 >> 4) & 7) * 256;
#pragma unroll
    for (int i = 0; i < 2; i++) {
        int f4  = threadIdx.x + (i << 9);
        int kb16 = f4 >> 5;
        int lane = f4 & 31;
        int lr = lane >> 2, tq = lane & 3;
        int c0 = (kb16 << 4) + (tq << 1);
        uint4 o;
        o.x = pk2(stg[lr    ][c0    ], stg[lr    ][c0 + 1]);
        o.y = pk2(stg[lr + 8][c0    ], stg[lr + 8][c0 + 1]);
        o.z = pk2(stg[lr    ][c0 + 8], stg[lr    ][c0 + 9]);
        o.w = pk2(stg[lr + 8][c0 + 8], stg[lr + 8][c0 + 9]);
        *(uint4*)(out + base + (size_t)kb16 * 2048 + lane * 8) = o;
    }
}

__global__ __launch_bounds__(512) void ln1_kernel(const float* __restrict__ x,
                                                  const float* __restrict__ skip,
                                                  const float* __restrict__ g1,
                                                  const float* __restrict__ b1,
                                                  __half* __restrict__ outxA,
                                                  __half* __restrict__ outsA) {
    __shared__ float stg[16][516];
    int warp = threadIdx.x >> 5, lane = threadIdx.x & 31;
    int row0 = blockIdx.x << 4;
    int nat  = wt_to_nat(row0 + warp);
    ln_row_st(x + (size_t)nat * CEMB, g1, b1, stg[warp], lane);
    __syncthreads();
    stg_writeA16(outxA, row0, stg);
    __syncthreads();
    ln_row_st(skip + (size_t)nat * CEMB, g1, b1, stg[warp], lane);
    __syncthreads();
    stg_writeA16(outsA, row0, stg);
}

__global__ __launch_bounds__(512) void ln2_kernel(const float* __restrict__ xin,
                                                  const float* __restrict__ g2,
                                                  const float* __restrict__ b2,
                                                  __half* __restrict__ outA) {
    __shared__ float stg[16][516];
    int warp = threadIdx.x >> 5, lane = threadIdx.x & 31;
    int row0 = blockIdx.x << 4;
    ln_row_st(xin + (size_t)(row0 + warp) * CEMB, g2, b2, stg[warp], lane);
    __syncthreads();
    stg_writeA16(outA, row0, stg);
}

// weight f32 natural [N][K] -> fp16 B-layout
__global__ __launch_bounds__(256) void wconvB_kernel(const float* __restrict__ w,
                                                     __half* __restrict__ out,
                                                     int K, int n8cnt) {
    int id = blockIdx.x * 256 + threadIdx.x;
    if (id >= n8cnt) return;
    size_t p0 = (size_t)id << 3;                 // half index
    int tp   = K << 7;                           // halves per 128-n tile
    int tile = (int)(p0 / tp);
    int rem  = (int)(p0 - (size_t)tile * tp);
    int kb16 = rem >> 11;
    int rem2 = rem & 2047;
    int ngrp = rem2 >> 8;
    int lane = (rem2 & 255) >> 3;
    int g = lane >> 2, tq = lane & 3;
    int n = (tile << 7) + (ngrp << 4) + g;
    int k = (kb16 << 4) + (tq << 1);
    uint4 o;
    o.x = pk2(w[(size_t)n * K + k],       w[(size_t)n * K + k + 1]);
    o.y = pk2(w[(size_t)n * K + k + 8],   w[(size_t)n * K + k + 9]);
    o.z = pk2(w[(size_t)(n + 8) * K + k],     w[(size_t)(n + 8) * K + k + 1]);
    o.w = pk2(w[(size_t)(n + 8) * K + k + 8], w[(size_t)(n + 8) * K + k + 9]);
    *(uint4*)(out + p0) = o;
}

// ---------------------------------------------------------------------------
// GEMM fp16: CTA 256x128, 8 warps (4m x 2n), warp 64x64, BK=64, 2 stages.
// Stage: A tile0 16KB | A tile1 16KB | B 16KB  (48KB)
// EPI: 0 +bias | 1 (+bias)*scale | 2 +res scatter nat | 3 gelu->A-layout | 4 +res
// ---------------------------------------------------------------------------
#define STG_BYTES 49152
#define GEMM_SMEM (2 * STG_BYTES)

template <int EPI>
__global__ __launch_bounds__(256) void gemm_h(const __half* __restrict__ A,
                                              const __half* __restrict__ W,
                                              const float* __restrict__ bias,
                                              float* __restrict__ out,
                                              const float* __restrict__ res,
                                              __half* __restrict__ outh,
                                              int N, int K) {
    extern __shared__ __align__(16) char smem[];
    const uint32_t sb = (uint32_t)__cvta_generic_to_shared(smem);
    const int tid  = threadIdx.x;
    const int warp = tid >> 5, lane = tid & 31;
    const int wm4  = warp >> 1;
    const int wn   = warp & 1;
    const int g    = lane >> 2, tq = lane & 3;
    const int bm   = blockIdx.y * 256;
    const int bn   = blockIdx.x * 128;

    const size_t aTile = (size_t)(bm >> 7) * 128 * K;
    const size_t bTile = (size_t)(bn >> 7) * 128 * K;

    float acc[4][8][4];
#pragma unroll
    for (int i = 0; i < 4; i++)
#pragma unroll
        for (int j = 0; j < 8; j++)
#pragma unroll
            for (int l = 0; l < 4; l++) acc[i][j][l] = 0.f;

    auto load_stage = [&](int s, int kb) {
        const uint32_t dst = sb + (uint32_t)s * STG_BYTES;
        const size_t ko = (size_t)kb * 8192;     // 4 kb16 blocks x 2048 halves
#pragma unroll
        for (int j = 0; j < 8; j++) {            // A: 2048 x 16B
            int f4 = tid + (j << 8);
            int tile = f4 >> 10;
            int rem  = f4 & 1023;
            cpa16(dst + (uint32_t)f4 * 16,
                  A + aTile + (size_t)tile * 128 * K + ko + ((size_t)rem << 3));
        }
#pragma unroll
        for (int j = 0; j < 4; j++) {            // B: 1024 x 16B
            int f4 = tid + (j << 8);
            cpa16(dst + 32768 + (uint32_t)f4 * 16, W + bTile + ko + ((size_t)f4 << 3));
        }
    };

    const int nkb = K >> 6;
    load_stage(0, 0); cpa_commit();
    load_stage(1, 1); cpa_commit();

    const uint32_t aOffW = ((uint32_t)(wm4 >> 1)) * 16384 + ((wm4 & 1) * 4) * 512 + lane * 16;
    const uint32_t bOffW = 32768 + (wn * 4) * 512 + lane * 16;

    for (int kb = 0; kb < nkb; kb++) {
        cpa_wait1();
        __syncthreads();
        const char* st = smem + (size_t)(kb & 1) * STG_BYTES;
#pragma unroll
        for (int kl = 0; kl < 4; kl++) {
            uint4 a[4], b[4];
#pragma unroll
            for (int mi = 0; mi < 4; mi++)
                a[mi] = *(const uint4*)(st + aOffW + kl * 4096 + mi * 512);
#pragma unroll
            for (int nj = 0; nj < 4; nj++)
                b[nj] = *(const uint4*)(st + bOffW + kl * 4096 + nj * 512);
#pragma unroll
            for (int mi = 0; mi < 4; mi++) {
                uint32_t ar[4] = {a[mi].x, a[mi].y, a[mi].z, a[mi].w};
#pragma unroll
                for (int nj = 0; nj < 4; nj++) {
                    mma16(acc[mi][2 * nj],     ar, b[nj].x, b[nj].y);
                    mma16(acc[mi][2 * nj + 1], ar, b[nj].z, b[nj].w);
                }
            }
        }
        __syncthreads();
        if (kb + 2 < nkb) load_stage(kb & 1, kb + 2);
        cpa_commit();
    }

    if (EPI == 3) {
        // gelu -> fp16 A-layout (fc2's A input), via f32 smem staging.
        cpa_wait0();
        __syncthreads();
        float* stg = (float*)smem;   // [128][132]
#pragma unroll
        for (int half = 0; half < 2; half++) {
            if ((wm4 >> 1) == half) {
                const int lrb = (wm4 & 1) * 64;
#pragma unroll
                for (int mi = 0; mi < 4; mi++)
#pragma unroll
                    for (int n8 = 0; n8 < 8; n8++) {
                        int lc = wn * 64 + n8 * 8 + (tq << 1);
                        float bv0 = bias[bn + lc], bv1 = bias[bn + lc + 1];
#pragma unroll
                        for (int hr = 0; hr < 2; hr++) {
                            int lr = lrb + mi * 16 + g + hr * 8;
                            float v0 = acc[mi][n8][hr * 2]     + bv0;
                            float v1 = acc[mi][n8][hr * 2 + 1] + bv1;
                            const float is2 = 0.70710678118654752f;
                            stg[lr * 132 + lc]     = 0.5f * v0 * (1.f + erff(v0 * is2));
                            stg[lr * 132 + lc + 1] = 0.5f * v1 * (1.f + erff(v1 * is2));
                        }
                    }
            }
            __syncthreads();
            size_t tbase = (size_t)((bm >> 7) + half) * 128 * N;
#pragma unroll
            for (int i = 0; i < 8; i++) {
                int f4   = tid + (i << 8);
                int kb16L = f4 >> 8;           // 0..7
                int grp  = (f4 >> 5) & 7;
                int ln2  = f4 & 31;
                int lr   = (grp << 4) + (ln2 >> 2);
                int c0   = (kb16L << 4) + ((ln2 & 3) << 1);
                uint4 o;
                o.x = pk2(stg[lr * 132 + c0],           stg[lr * 132 + c0 + 1]);
                o.y = pk2(stg[(lr + 8) * 132 + c0],     stg[(lr + 8) * 132 + c0 + 1]);
                o.z = pk2(stg[lr * 132 + c0 + 8],       stg[lr * 132 + c0 + 9]);
                o.w = pk2(stg[(lr + 8) * 132 + c0 + 8], stg[(lr + 8) * 132 + c0 + 9]);
                *(uint4*)(outh + tbase + (size_t)((bn >> 4) + kb16L) * 2048
                          + (size_t)grp * 256 + ln2 * 8) = o;
            }
            __syncthreads();
        }
        return;
    }

#pragma unroll
    for (int mi = 0; mi < 4; mi++) {
#pragma unroll
        for (int hr = 0; hr < 2; hr++) {
            int r = bm + wm4 * 64 + mi * 16 + g + hr * 8;
            size_t obase;
            if (EPI == 2) obase = (size_t)wt_to_nat(r) * CEMB;
            else          obase = (size_t)r * N;
#pragma unroll
            for (int n8 = 0; n8 < 8; n8++) {
                int c = bn + wn * 64 + n8 * 8 + (tq << 1);
                float v0 = acc[mi][n8][hr * 2]     + bias[c];
                float v1 = acc[mi][n8][hr * 2 + 1] + bias[c + 1];
                if (EPI == 1) {
                    const float sc = 0.17677669529663687f;
                    v0 *= sc; v1 *= sc;
                } else if (EPI == 2 || EPI == 4) {
                    v0 += res[obase + c];
                    v1 += res[obase + c + 1];
                }
                *(float2*)(out + obase + c) = make_float2(v0, v1);
            }
        }
    }
}

// ---------------------------------------------------------------------------
// Windowed attention (fp32). Output -> fp16 A-layout.
// ---------------------------------------------------------------------------
__global__ __launch_bounds__(256) void attn_kernel(const float* __restrict__ q,
                                                   const float* __restrict__ kv,
                                                   const float* __restrict__ rb,
                                                   __half* __restrict__ outA) {
    __shared__ __align__(16) float sq [64][36];
    __shared__ __align__(16) float skT[32][68];
    __shared__ __align__(16) float sv [64][36];
    __shared__ float sc[64][65];
    __shared__ float so[64][33];

    const int tid = threadIdx.x;
    const int win = blockIdx.x;
    const int wi  = win & 63;
    const int wr  = wi >> 3, wc = wi & 7;
    const int base = win << 6;
    const int h0  = blockIdx.y << 2;
    const size_t tbase = (size_t)(win >> 1) * (128 * 512);
    const int grpBase = (win & 1) * 4;

    for (int h = h0; h < h0 + 4; h++) {
        for (int i = tid; i < 2048; i += 256) {
            int n = i >> 5, d = i & 31;
            sq[n][d] = q [(size_t)(base + n) * 512  + h * 32 + d];
            skT[d][n]= kv[(size_t)(base + n) * 1024 + h * 32 + d];
            sv[n][d] = kv[(size_t)(base + n) * 1024 + 512 + h * 32 + d];
        }
        __syncthreads();

        const int tn = (tid >> 4) << 2;
        const int tm = (tid & 15) << 2;
        float rs[4][4] = {};
        for (int dc = 0; dc < 32; dc += 4) {
            float a[4][4], bb[4][4];
#pragma unroll
            for (int i = 0; i < 4; i++)
                *(float4*)a[i] = *(const float4*)&sq[tn + i][dc];
#pragma unroll
            for (int l = 0; l < 4; l++)
                *(float4*)bb[l] = *(const float4*)&skT[dc + l][tm];
#pragma unroll
            for (int i = 0; i < 4; i++)
#pragma unroll
                for (int j = 0; j < 4; j++)
#pragma unroll
                    for (int l = 0; l < 4; l++)
                        rs[i][j] += a[i][l] * bb[l][j];
        }
#pragma unroll
        for (int i = 0; i < 4; i++) {
            int n = tn + i;
            int cn = 15 * (n >> 3) + (n & 7);
            int rhn = (wr == 7) ? (((n >> 3) < 4) ? 1 : 2) : 0;
            int rwn = (wc == 7) ? (((n & 7)  < 4) ? 1 : 2) : 0;
            int regn = rhn * 3 + rwn;
#pragma unroll
            for (int j = 0; j < 4; j++) {
                int m = tm + j;
                int m2 = 63 - m;
                int cm = 15 * (m2 >> 3) + (m2 & 7);
                float bv = rb[(cn + cm) * 16 + h];
                int rhm = (wr == 7) ? (((m >> 3) < 4) ? 1 : 2) : 0;
                int rwm = (wc == 7) ? (((m & 7)  < 4) ? 1 : 2) : 0;
                float msk = ((rhm * 3 + rwm) != regn) ? -100.f : 0.f;
                sc[n][m] = rs[i][j] + bv + msk;
            }
        }
        __syncthreads();

        {
            int row = tid >> 2, sub = tid & 3;
            float mx = -1e30f;
#pragma unroll
            for (int j = 0; j < 16; j++) mx = fmaxf(mx, sc[row][sub + 4 * j]);
            mx = fmaxf(mx, __shfl_xor_sync(0xffffffffu, mx, 1));
            mx = fmaxf(mx, __shfl_xor_sync(0xffffffffu, mx, 2));
            float ev[16], sm = 0.f;
#pragma unroll
            for (int j = 0; j < 16; j++) {
                ev[j] = expf(sc[row][sub + 4 * j] - mx);
                sm += ev[j];
            }
            sm += __shfl_xor_sync(0xffffffffu, sm, 1);
            sm += __shfl_xor_sync(0xffffffffu, sm, 2);
            float inv = 1.f / sm;
#pragma unroll
            for (int j = 0; j < 16; j++) sc[row][sub + 4 * j] = ev[j] * inv;
        }
        __syncthreads();

        {
            int n0 = (tid >> 3) << 1;
            int d0 = (tid & 7) << 2;
            float o0[4] = {}, o1[4] = {};
            for (int m = 0; m < 64; m++) {
                float4 vv = *(const float4*)&sv[m][d0];
                float s0 = sc[n0][m], s1 = sc[n0 + 1][m];
                o0[0] += s0 * vv.x; o0[1] += s0 * vv.y; o0[2] += s0 * vv.z; o0[3] += s0 * vv.w;
                o1[0] += s1 * vv.x; o1[1] += s1 * vv.y; o1[2] += s1 * vv.z; o1[3] += s1 * vv.w;
            }
#pragma unroll
            for (int l = 0; l < 4; l++) {
                so[n0][d0 + l]     = o0[l];
                so[n0 + 1][d0 + l] = o1[l];
            }
        }
        __syncthreads();

        // fp16 A-layout write: 2 kb16 x 4 rowgrp x 32 lanes = 256 stores
        {
            int kb16L = tid >> 7;            // 0..1
            int grpL  = (tid >> 5) & 3;      // 0..3
            int ln2   = tid & 31;
            int lr    = (grpL << 4) + (ln2 >> 2);
            int c0    = (kb16L << 4) + ((ln2 & 3) << 1);
            uint4 o;
            o.x = pk2(so[lr][c0],         so[lr][c0 + 1]);
            o.y = pk2(so[lr + 8][c0],     so[lr + 8][c0 + 1]);
            o.z = pk2(so[lr][c0 + 8],     so[lr][c0 + 9]);
            o.w = pk2(so[lr + 8][c0 + 8], so[lr + 8][c0 + 9]);
            *(uint4*)(outA + tbase + (size_t)(2 * h + kb16L) * 2048
                      + (size_t)(grpBase + grpL) * 256 + ln2 * 8) = o;
        }
        __syncthreads();
    }
}

// ---------------------------------------------------------------------------
extern "C" void kernel_launch(void* const* d_in, const int* in_sizes, int n_in,
                              void* d_out, int out_size) {
    const float* x      = (const float*)d_in[0];
    const float* skip   = (const float*)d_in[1];
    const float* n1g    = (const float*)d_in[2];
    const float* n1b    = (const float*)d_in[3];
    const float* w_qkv  = (const float*)d_in[4];
    const float* b_qkv  = (const float*)d_in[5];
    const float* w_skip = (const float*)d_in[6];
    const float* b_skip = (const float*)d_in[7];
    const float* relb   = (const float*)d_in[8];
    const float* w_proj = (const float*)d_in[9];
    const float* b_proj = (const float*)d_in[10];
    const float* n2g    = (const float*)d_in[11];
    const float* n2b    = (const float*)d_in[12];
    const float* w_fc1  = (const float*)d_in[13];
    const float* b_fc1  = (const float*)d_in[14];
    const float* w_fc2  = (const float*)d_in[15];
    const float* b_fc2  = (const float*)d_in[16];
    float* outp = (float*)d_out;

    __half *axA, *asA, *hA, *wqB, *wsB, *wpB, *w1B, *w2B;
    float *kvb, *qb, *xres;
    cudaGetSymbolAddress((void**)&axA, g_axA);
    cudaGetSymbolAddress((void**)&asA, g_asA);
    cudaGetSymbolAddress((void**)&kvb, g_kv);
    cudaGetSymbolAddress((void**)&qb,  g_q);
    cudaGetSymbolAddress((void**)&xres, g_xres);
    cudaGetSymbolAddress((void**)&hA,  g_hA);
    cudaGetSymbolAddress((void**)&wqB, g_wqkvB);
    cudaGetSymbolAddress((void**)&wsB, g_wskipB);
    cudaGetSymbolAddress((void**)&wpB, g_wprojB);
    cudaGetSymbolAddress((void**)&w1B, g_wfc1B);
    cudaGetSymbolAddress((void**)&w2B, g_wfc2B);

    cudaFuncSetAttribute(gemm_h<0>, cudaFuncAttributeMaxDynamicSharedMemorySize, GEMM_SMEM);
    cudaFuncSetAttribute(gemm_h<1>, cudaFuncAttributeMaxDynamicSharedMemorySize, GEMM_SMEM);
    cudaFuncSetAttribute(gemm_h<2>, cudaFuncAttributeMaxDynamicSharedMemorySize, GEMM_SMEM);
    cudaFuncSetAttribute(gemm_h<3>, cudaFuncAttributeMaxDynamicSharedMemorySize, GEMM_SMEM);
    cudaFuncSetAttribute(gemm_h<4>, cudaFuncAttributeMaxDynamicSharedMemorySize, GEMM_SMEM);

    wconvB_kernel<<<(1024*512/8 + 255)/256, 256>>>(w_qkv,  wqB, 512,  1024*512/8);
    wconvB_kernel<<<(512*512/8  + 255)/256, 256>>>(w_skip, wsB, 512,  512*512/8);
    wconvB_kernel<<<(512*512/8  + 255)/256, 256>>>(w_proj, wpB, 512,  512*512/8);
    wconvB_kernel<<<(2048*512/8 + 255)/256, 256>>>(w_fc1,  w1B, 512,  2048*512/8);
    wconvB_kernel<<<(512*2048/8 + 255)/256, 256>>>(w_fc2,  w2B, 2048, 512*2048/8);

    ln1_kernel<<<4096, 512>>>(x, skip, n1g, n1b, axA, asA);
    gemm_h<0><<<dim3(8, 256), 256, GEMM_SMEM>>>(axA, wqB, b_qkv, kvb, nullptr, nullptr, 1024, 512);
    gemm_h<1><<<dim3(4, 256), 256, GEMM_SMEM>>>(asA, wsB, b_skip, qb, nullptr, nullptr, 512, 512);
    attn_kernel<<<dim3(1024, 4), 256>>>(qb, kvb, relb, asA);
    gemm_h<2><<<dim3(4, 256), 256, GEMM_SMEM>>>(asA, wpB, b_proj, xres, x, nullptr, 512, 512);
    ln2_kernel<<<4096, 512>>>(xres, n2g, n2b, axA);
    gemm_h<3><<<dim3(16, 256), 256, GEMM_SMEM>>>(axA, w1B, b_fc1, nullptr, nullptr, hA, 2048, 512);
    gemm_h<4><<<dim3(4, 256), 256, GEMM_SMEM>>>(hA, w2B, b_fc2, outp, xres, nullptr, 512, 2048);
    (void)in_sizes; (void)n_in; (void)out_size;
}

// round 9
// speedup vs baseline: 2.6567x; 1.1138x over previous
#include <cuda_runtime.h>
#include <cuda_fp16.h>
#include <cstdint>

// ---------------------------------------------------------------------------
// SwinBlock sm_103a round 8: fp16 MMA everywhere.
//  - GEMMs: as round 7 (fp16 m16n8k16, fragment-order gmem, BK=64, 2-stage).
//  - q/kv now emitted fp16 natural layout by GEMM epilogues.
//  - Attention: QK^T and P.V via m16n8k16 MMA; softmax fp32; P fp16.
// ---------------------------------------------------------------------------

#define TOK   65536
#define CEMB  512
#define FFN   2048

__device__ __half g_axA [(size_t)TOK * CEMB];
__device__ __half g_asA [(size_t)TOK * CEMB];
__device__ __half g_kv  [(size_t)TOK * 1024];
__device__ __half g_q   [(size_t)TOK * CEMB];
__device__ float  g_xres[(size_t)TOK * CEMB];
__device__ __half g_hA  [(size_t)TOK * FFN];
__device__ __half g_wqkvB[1024 * 512];
__device__ __half g_wskipB[512 * 512];
__device__ __half g_wprojB[512 * 512];
__device__ __half g_wfc1B[2048 * 512];
__device__ __half g_wfc2B[512 * 2048];

__device__ __forceinline__ int wt_to_nat(int wt) {
    int n   = wt & 63;
    int win = wt >> 6;
    int wi  = win & 63;
    int b   = win >> 6;
    int hp  = ((wi >> 3) << 3) + (n >> 3);
    int wp  = ((wi & 7)  << 3) + (n & 7);
    int h   = (hp + 4) & 63;
    int w   = (wp + 4) & 63;
    return (b << 12) + (h << 6) + w;
}

__device__ __forceinline__ uint32_t pk2(float a, float b) {
    __half2 h = __floats2half2_rn(a, b);
    return *(uint32_t*)&h;
}

__device__ __forceinline__ void mma16(float c[4], const uint32_t a[4],
                                      uint32_t b0, uint32_t b1) {
    asm volatile(
        "mma.sync.aligned.m16n8k16.row.col.f32.f16.f16.f32 "
        "{%0,%1,%2,%3}, {%4,%5,%6,%7}, {%8,%9}, {%0,%1,%2,%3};\n"
        : "+f"(c[0]), "+f"(c[1]), "+f"(c[2]), "+f"(c[3])
        : "r"(a[0]), "r"(a[1]), "r"(a[2]), "r"(a[3]), "r"(b0), "r"(b1));
}

__device__ __forceinline__ void cpa16(uint32_t dst, const void* src) {
    asm volatile("cp.async.cg.shared.global [%0], [%1], 16;\n" :: "r"(dst), "l"(src));
}
__device__ __forceinline__ void cpa_commit() { asm volatile("cp.async.commit_group;\n"); }
__device__ __forceinline__ void cpa_wait1()  { asm volatile("cp.async.wait_group 1;\n"); }
__device__ __forceinline__ void cpa_wait0()  { asm volatile("cp.async.wait_group 0;\n"); }

// ---------------------------------------------------------------------------
// LayerNorm -> f32 smem staging -> fp16 A-layout write.
// ---------------------------------------------------------------------------
__device__ __forceinline__ void ln_row_st(const float* __restrict__ in,
                                          const float* __restrict__ g,
                                          const float* __restrict__ b,
                                          float* __restrict__ stgrow, int lane) {
    float4 v[4];
    float s = 0.f, sq = 0.f;
#pragma unroll
    for (int j = 0; j < 4; j++) {
        v[j] = *(const float4*)(in + (((j << 5) + lane) << 2));
        s  += v[j].x + v[j].y + v[j].z + v[j].w;
        sq += v[j].x*v[j].x + v[j].y*v[j].y + v[j].z*v[j].z + v[j].w*v[j].w;
    }
#pragma unroll
    for (int o = 16; o; o >>= 1) {
        s  += __shfl_xor_sync(0xffffffffu, s, o);
        sq += __shfl_xor_sync(0xffffffffu, sq, o);
    }
    float mean = s * (1.f / 512.f);
    float var  = sq * (1.f / 512.f) - mean * mean;
    float rstd = rsqrtf(var + 1e-5f);
#pragma unroll
    for (int j = 0; j < 4; j++) {
        int off = (((j << 5) + lane) << 2);
        float4 gg = *(const float4*)(g + off);
        float4 bb = *(const float4*)(b + off);
        stgrow[off + 0] = (v[j].x - mean) * rstd * gg.x + bb.x;
        stgrow[off + 1] = (v[j].y - mean) * rstd * gg.y + bb.y;
        stgrow[off + 2] = (v[j].z - mean) * rstd * gg.z + bb.z;
        stgrow[off + 3] = (v[j].w - mean) * rstd * gg.w + bb.w;
    }
}

__device__ __forceinline__ void stg_writeA16(__half* __restrict__ out, int row0,
                                             const float (*stg)[516]) {
    size_t base = (size_t)(row0 >> 7) * (128 * 512) + (size_t)((row0 >> 4) & 7) * 256;
#pragma unroll
    for (int i = 0; i < 2; i++) {
        int f4  = threadIdx.x + (i << 9);
        int kb16 = f4 >> 5;
        int lane = f4 & 31;
        int lr = lane >> 2, tq = lane & 3;
        int c0 = (kb16 << 4) + (tq << 1);
        uint4 o;
        o.x = pk2(stg[lr    ][c0    ], stg[lr    ][c0 + 1]);
        o.y = pk2(stg[lr + 8][c0    ], stg[lr + 8][c0 + 1]);
        o.z = pk2(stg[lr    ][c0 + 8], stg[lr    ][c0 + 9]);
        o.w = pk2(stg[lr + 8][c0 + 8], stg[lr + 8][c0 + 9]);
        *(uint4*)(out + base + (size_t)kb16 * 2048 + lane * 8) = o;
    }
}

__global__ __launch_bounds__(512) void ln1_kernel(const float* __restrict__ x,
                                                  const float* __restrict__ skip,
                                                  const float* __restrict__ g1,
                                                  const float* __restrict__ b1,
                                                  __half* __restrict__ outxA,
                                                  __half* __restrict__ outsA) {
    __shared__ float stg[16][516];
    int warp = threadIdx.x >> 5, lane = threadIdx.x & 31;
    int row0 = blockIdx.x << 4;
    int nat  = wt_to_nat(row0 + warp);
    ln_row_st(x + (size_t)nat * CEMB, g1, b1, stg[warp], lane);
    __syncthreads();
    stg_writeA16(outxA, row0, stg);
    __syncthreads();
    ln_row_st(skip + (size_t)nat * CEMB, g1, b1, stg[warp], lane);
    __syncthreads();
    stg_writeA16(outsA, row0, stg);
}

__global__ __launch_bounds__(512) void ln2_kernel(const float* __restrict__ xin,
                                                  const float* __restrict__ g2,
                                                  const float* __restrict__ b2,
                                                  __half* __restrict__ outA) {
    __shared__ float stg[16][516];
    int warp = threadIdx.x >> 5, lane = threadIdx.x & 31;
    int row0 = blockIdx.x << 4;
    ln_row_st(xin + (size_t)(row0 + warp) * CEMB, g2, b2, stg[warp], lane);
    __syncthreads();
    stg_writeA16(outA, row0, stg);
}

__global__ __launch_bounds__(256) void wconvB_kernel(const float* __restrict__ w,
                                                     __half* __restrict__ out,
                                                     int K, int n8cnt) {
    int id = blockIdx.x * 256 + threadIdx.x;
    if (id >= n8cnt) return;
    size_t p0 = (size_t)id << 3;
    int tp   = K << 7;
    int tile = (int)(p0 / tp);
    int rem  = (int)(p0 - (size_t)tile * tp);
    int kb16 = rem >> 11;
    int rem2 = rem & 2047;
    int ngrp = rem2 >> 8;
    int lane = (rem2 & 255) >> 3;
    int g = lane >> 2, tq = lane & 3;
    int n = (tile << 7) + (ngrp << 4) + g;
    int k = (kb16 << 4) + (tq << 1);
    uint4 o;
    o.x = pk2(w[(size_t)n * K + k],       w[(size_t)n * K + k + 1]);
    o.y = pk2(w[(size_t)n * K + k + 8],   w[(size_t)n * K + k + 9]);
    o.z = pk2(w[(size_t)(n + 8) * K + k],     w[(size_t)(n + 8) * K + k + 1]);
    o.w = pk2(w[(size_t)(n + 8) * K + k + 8], w[(size_t)(n + 8) * K + k + 9]);
    *(uint4*)(out + p0) = o;
}

// ---------------------------------------------------------------------------
// GEMM fp16. EPI: 0 +bias->half nat | 1 (+bias)*scale->half nat
//               | 2 +res scatter f32 nat | 3 gelu->A-layout | 4 +res f32
// ---------------------------------------------------------------------------
#define STG_BYTES 49152
#define GEMM_SMEM (2 * STG_BYTES)

template <int EPI>
__global__ __launch_bounds__(256) void gemm_h(const __half* __restrict__ A,
                                              const __half* __restrict__ W,
                                              const float* __restrict__ bias,
                                              float* __restrict__ out,
                                              const float* __restrict__ res,
                                              __half* __restrict__ outh,
                                              int N, int K) {
    extern __shared__ __align__(16) char smem[];
    const uint32_t sb = (uint32_t)__cvta_generic_to_shared(smem);
    const int tid  = threadIdx.x;
    const int warp = tid >> 5, lane = tid & 31;
    const int wm4  = warp >> 1;
    const int wn   = warp & 1;
    const int g    = lane >> 2, tq = lane & 3;
    const int bm   = blockIdx.y * 256;
    const int bn   = blockIdx.x * 128;

    const size_t aTile = (size_t)(bm >> 7) * 128 * K;
    const size_t bTile = (size_t)(bn >> 7) * 128 * K;

    float acc[4][8][4];
#pragma unroll
    for (int i = 0; i < 4; i++)
#pragma unroll
        for (int j = 0; j < 8; j++)
#pragma unroll
            for (int l = 0; l < 4; l++) acc[i][j][l] = 0.f;

    auto load_stage = [&](int s, int kb) {
        const uint32_t dst = sb + (uint32_t)s * STG_BYTES;
        const size_t ko = (size_t)kb * 8192;
#pragma unroll
        for (int j = 0; j < 8; j++) {
            int f4 = tid + (j << 8);
            int tile = f4 >> 10;
            int rem  = f4 & 1023;
            cpa16(dst + (uint32_t)f4 * 16,
                  A + aTile + (size_t)tile * 128 * K + ko + ((size_t)rem << 3));
        }
#pragma unroll
        for (int j = 0; j < 4; j++) {
            int f4 = tid + (j << 8);
            cpa16(dst + 32768 + (uint32_t)f4 * 16, W + bTile + ko + ((size_t)f4 << 3));
        }
    };

    const int nkb = K >> 6;
    load_stage(0, 0); cpa_commit();
    load_stage(1, 1); cpa_commit();

    const uint32_t aOffW = ((uint32_t)(wm4 >> 1)) * 16384 + ((wm4 & 1) * 4) * 512 + lane * 16;
    const uint32_t bOffW = 32768 + (wn * 4) * 512 + lane * 16;

    for (int kb = 0; kb < nkb; kb++) {
        cpa_wait1();
        __syncthreads();
        const char* st = smem + (size_t)(kb & 1) * STG_BYTES;
#pragma unroll
        for (int kl = 0; kl < 4; kl++) {
            uint4 a[4], b[4];
#pragma unroll
            for (int mi = 0; mi < 4; mi++)
                a[mi] = *(const uint4*)(st + aOffW + kl * 4096 + mi * 512);
#pragma unroll
            for (int nj = 0; nj < 4; nj++)
                b[nj] = *(const uint4*)(st + bOffW + kl * 4096 + nj * 512);
#pragma unroll
            for (int mi = 0; mi < 4; mi++) {
                uint32_t ar[4] = {a[mi].x, a[mi].y, a[mi].z, a[mi].w};
#pragma unroll
                for (int nj = 0; nj < 4; nj++) {
                    mma16(acc[mi][2 * nj],     ar, b[nj].x, b[nj].y);
                    mma16(acc[mi][2 * nj + 1], ar, b[nj].z, b[nj].w);
                }
            }
        }
        __syncthreads();
        if (kb + 2 < nkb) load_stage(kb & 1, kb + 2);
        cpa_commit();
    }

    if (EPI == 3) {
        cpa_wait0();
        __syncthreads();
        float* stg = (float*)smem;   // [128][132]
#pragma unroll
        for (int half = 0; half < 2; half++) {
            if ((wm4 >> 1) == half) {
                const int lrb = (wm4 & 1) * 64;
#pragma unroll
                for (int mi = 0; mi < 4; mi++)
#pragma unroll
                    for (int n8 = 0; n8 < 8; n8++) {
                        int lc = wn * 64 + n8 * 8 + (tq << 1);
                        float bv0 = bias[bn + lc], bv1 = bias[bn + lc + 1];
#pragma unroll
                        for (int hr = 0; hr < 2; hr++) {
                            int lr = lrb + mi * 16 + g + hr * 8;
                            float v0 = acc[mi][n8][hr * 2]     + bv0;
                            float v1 = acc[mi][n8][hr * 2 + 1] + bv1;
                            const float is2 = 0.70710678118654752f;
                            stg[lr * 132 + lc]     = 0.5f * v0 * (1.f + erff(v0 * is2));
                            stg[lr * 132 + lc + 1] = 0.5f * v1 * (1.f + erff(v1 * is2));
                        }
                    }
            }
            __syncthreads();
            size_t tbase = (size_t)((bm >> 7) + half) * 128 * N;
#pragma unroll
            for (int i = 0; i < 8; i++) {
                int f4   = tid + (i << 8);
                int kb16L = f4 >> 8;
                int grp  = (f4 >> 5) & 7;
                int ln2  = f4 & 31;
                int lr   = (grp << 4) + (ln2 >> 2);
                int c0   = (kb16L << 4) + ((ln2 & 3) << 1);
                uint4 o;
                o.x = pk2(stg[lr * 132 + c0],           stg[lr * 132 + c0 + 1]);
                o.y = pk2(stg[(lr + 8) * 132 + c0],     stg[(lr + 8) * 132 + c0 + 1]);
                o.z = pk2(stg[lr * 132 + c0 + 8],       stg[lr * 132 + c0 + 9]);
                o.w = pk2(stg[(lr + 8) * 132 + c0 + 8], stg[(lr + 8) * 132 + c0 + 9]);
                *(uint4*)(outh + tbase + (size_t)((bn >> 4) + kb16L) * 2048
                          + (size_t)grp * 256 + ln2 * 8) = o;
            }
            __syncthreads();
        }
        return;
    }

#pragma unroll
    for (int mi = 0; mi < 4; mi++) {
#pragma unroll
        for (int hr = 0; hr < 2; hr++) {
            int r = bm + wm4 * 64 + mi * 16 + g + hr * 8;
            size_t obase;
            if (EPI == 2) obase = (size_t)wt_to_nat(r) * CEMB;
            else          obase = (size_t)r * N;
#pragma unroll
            for (int n8 = 0; n8 < 8; n8++) {
                int c = bn + wn * 64 + n8 * 8 + (tq << 1);
                float v0 = acc[mi][n8][hr * 2]     + bias[c];
                float v1 = acc[mi][n8][hr * 2 + 1] + bias[c + 1];
                if (EPI == 0) {
                    *(uint32_t*)(outh + obase + c) = pk2(v0, v1);
                } else if (EPI == 1) {
                    const float sc = 0.17677669529663687f;
                    *(uint32_t*)(outh + obase + c) = pk2(v0 * sc, v1 * sc);
                } else {
                    v0 += res[obase + c];
                    v1 += res[obase + c + 1];
                    *(float2*)(out + obase + c) = make_float2(v0, v1);
                }
            }
        }
    }
}

// ---------------------------------------------------------------------------
// Windowed attention via fp16 MMA. Grid (1024 win, 4 head-groups), 256 thr.
// smem rows padded to 40 halves -> conflict-free fragment LDS.32.
// ---------------------------------------------------------------------------
__global__ __launch_bounds__(256) void attn_kernel(const __half* __restrict__ q,
                                                   const __half* __restrict__ kv,
                                                   const float* __restrict__ rb,
                                                   __half* __restrict__ outA) {
    __shared__ __align__(16) __half sqh[64][40];
    __shared__ __align__(16) __half skh[64][40];
    __shared__ __align__(16) __half svT[32][40];   // [d][key]... key up to 64!
    __shared__ __align__(16) __half svT2[32][40];  // keys 32..63
    __shared__ float  sc[64][65];
    __shared__ __half sp[64][40];
    __shared__ __half sp2[64][40];
    __shared__ float  so[64][33];

    const int tid  = threadIdx.x;
    const int warp = tid >> 5, lane = tid & 31;
    const int g    = lane >> 2, tq = lane & 3;
    const int wm   = warp >> 1;       // 0..3
    const int wn   = warp & 1;        // 0..1
    const int win  = blockIdx.x;
    const int wi   = win & 63;
    const int wr   = wi >> 3, wc = wi & 7;
    const int base = win << 6;
    const int h0   = blockIdx.y << 2;
    const size_t tbase = (size_t)(win >> 1) * (128 * 512);
    const int grpBase = (win & 1) * 4;

    for (int h = h0; h < h0 + 4; h++) {
        // ---- load Q,K (uint4) and V (transposed, split into two 32-key tiles)
        {
            int rown = tid >> 2;            // 0..63
            int ch   = tid & 3;             // 16B chunk
            *(uint4*)&sqh[rown][ch << 3] =
                *(const uint4*)(q  + (size_t)(base + rown) * 512  + h * 32 + (ch << 3));
            *(uint4*)&skh[rown][ch << 3] =
                *(const uint4*)(kv + (size_t)(base + rown) * 1024 + h * 32 + (ch << 3));
            // V transpose: each thread 4 half2 (8 d-values for one key... )
            // thread handles key=rown, d pair chunk ch: d = ch*8..ch*8+7
            const __half* vsrc = kv + (size_t)(base + rown) * 1024 + 512 + h * 32;
#pragma unroll
            for (int dd = 0; dd < 8; dd += 1) {
                int d = (ch << 3) + dd;
                __half vv = vsrc[d];
                if (rown < 32) svT [d][rown]      = vv;
                else           svT2[d][rown - 32] = vv;
            }
        }
        __syncthreads();

        // ---- S = Q K^T (+bias+mask) -> sc
        {
            const int tn0 = wm << 4;
            const int n00 = wn << 5;
            uint32_t aF[2][4];
#pragma unroll
            for (int ks = 0; ks < 2; ks++) {
                int k0 = ks << 4;
                aF[ks][0] = *(const uint32_t*)&sqh[tn0 + g    ][(tq << 1) + k0];
                aF[ks][1] = *(const uint32_t*)&sqh[tn0 + g + 8][(tq << 1) + k0];
                aF[ks][2] = *(const uint32_t*)&sqh[tn0 + g    ][(tq << 1) + 8 + k0];
                aF[ks][3] = *(const uint32_t*)&sqh[tn0 + g + 8][(tq << 1) + 8 + k0];
            }
            float accS[4][4];
#pragma unroll
            for (int nj = 0; nj < 4; nj++) {
#pragma unroll
                for (int l = 0; l < 4; l++) accS[nj][l] = 0.f;
#pragma unroll
                for (int ks = 0; ks < 2; ks++) {
                    int k0 = ks << 4;
                    uint32_t b0 = *(const uint32_t*)&skh[n00 + (nj << 3) + g][(tq << 1) + k0];
                    uint32_t b1 = *(const uint32_t*)&skh[n00 + (nj << 3) + g][(tq << 1) + 8 + k0];
                    mma16(accS[nj], aF[ks], b0, b1);
                }
            }
            // epilogue: bias + mask -> sc
#pragma unroll
            for (int nj = 0; nj < 4; nj++) {
#pragma unroll
                for (int hr = 0; hr < 2; hr++) {
                    int n = tn0 + g + (hr << 3);
                    int cn = 15 * (n >> 3) + (n & 7);
                    int rhn = (wr == 7) ? (((n >> 3) < 4) ? 1 : 2) : 0;
                    int rwn = (wc == 7) ? (((n & 7)  < 4) ? 1 : 2) : 0;
                    int regn = rhn * 3 + rwn;
#pragma unroll
                    for (int cc = 0; cc < 2; cc++) {
                        int m = n00 + (nj << 3) + (tq << 1) + cc;
                        int m2 = 63 - m;
                        int cm = 15 * (m2 >> 3) + (m2 & 7);
                        float bv = rb[(cn + cm) * 16 + h];
                        int rhm = (wr == 7) ? (((m >> 3) < 4) ? 1 : 2) : 0;
                        int rwm = (wc == 7) ? (((m & 7)  < 4) ? 1 : 2) : 0;
                        float msk = ((rhm * 3 + rwm) != regn) ? -100.f : 0.f;
                        sc[n][m] = accS[nj][hr * 2 + cc] + bv + msk;
                    }
                }
            }
        }
        __syncthreads();

        // ---- softmax (fp32) -> sp (fp16, split 32-key halves)
        {
            int row = tid >> 2, sub = tid & 3;
            float mx = -1e30f;
#pragma unroll
            for (int j = 0; j < 16; j++) mx = fmaxf(mx, sc[row][sub + 4 * j]);
            mx = fmaxf(mx, __shfl_xor_sync(0xffffffffu, mx, 1));
            mx = fmaxf(mx, __shfl_xor_sync(0xffffffffu, mx, 2));
            float ev[16], sm = 0.f;
#pragma unroll
            for (int j = 0; j < 16; j++) {
                ev[j] = expf(sc[row][sub + 4 * j] - mx);
                sm += ev[j];
            }
            sm += __shfl_xor_sync(0xffffffffu, sm, 1);
            sm += __shfl_xor_sync(0xffffffffu, sm, 2);
            float inv = 1.f / sm;
#pragma unroll
            for (int j = 0; j < 16; j++) {
                int col = sub + 4 * j;
                __half hv = __float2half_rn(ev[j] * inv);
                if (col < 32) sp [row][col]      = hv;
                else          sp2[row][col - 32] = hv;
            }
        }
        __syncthreads();

        // ---- O = P V -> so
        {
            const int r0 = wm << 4;
            const int d0 = wn << 4;
            float accO[2][4];
#pragma unroll
            for (int nj = 0; nj < 2; nj++)
#pragma unroll
                for (int l = 0; l < 4; l++) accO[nj][l] = 0.f;
#pragma unroll
            for (int kk = 0; kk < 4; kk++) {
                int k0 = (kk & 1) << 4;
                const __half (*spp)[40] = (kk < 2) ? sp  : sp2;
                const __half (*svv)[40] = (kk < 2) ? svT : svT2;
                uint32_t aP[4];
                aP[0] = *(const uint32_t*)&spp[r0 + g    ][(tq << 1) + k0];
                aP[1] = *(const uint32_t*)&spp[r0 + g + 8][(tq << 1) + k0];
                aP[2] = *(const uint32_t*)&spp[r0 + g    ][(tq << 1) + 8 + k0];
                aP[3] = *(const uint32_t*)&spp[r0 + g + 8][(tq << 1) + 8 + k0];
#pragma unroll
                for (int nj = 0; nj < 2; nj++) {
                    uint32_t b0 = *(const uint32_t*)&svv[d0 + (nj << 3) + g][(tq << 1) + k0];
                    uint32_t b1 = *(const uint32_t*)&svv[d0 + (nj << 3) + g][(tq << 1) + 8 + k0];
                    mma16(accO[nj], aP, b0, b1);
                }
            }
#pragma unroll
            for (int nj = 0; nj < 2; nj++)
#pragma unroll
                for (int hr = 0; hr < 2; hr++) {
                    int rr = r0 + g + (hr << 3);
                    int dd = d0 + (nj << 3) + (tq << 1);
                    so[rr][dd]     = accO[nj][hr * 2];
                    so[rr][dd + 1] = accO[nj][hr * 2 + 1];
                }
        }
        __syncthreads();

        // ---- so -> fp16 A-layout
        {
            int kb16L = tid >> 7;
            int grpL  = (tid >> 5) & 3;
            int ln2   = tid & 31;
            int lr    = (grpL << 4) + (ln2 >> 2);
            int c0    = (kb16L << 4) + ((ln2 & 3) << 1);
            uint4 o;
            o.x = pk2(so[lr][c0],         so[lr][c0 + 1]);
            o.y = pk2(so[lr + 8][c0],     so[lr + 8][c0 + 1]);
            o.z = pk2(so[lr][c0 + 8],     so[lr][c0 + 9]);
            o.w = pk2(so[lr + 8][c0 + 8], so[lr + 8][c0 + 9]);
            *(uint4*)(outA + tbase + (size_t)(2 * h + kb16L) * 2048
                      + (size_t)(grpBase + grpL) * 256 + ln2 * 8) = o;
        }
        __syncthreads();
    }
}

// ---------------------------------------------------------------------------
extern "C" void kernel_launch(void* const* d_in, const int* in_sizes, int n_in,
                              void* d_out, int out_size) {
    const float* x      = (const float*)d_in[0];
    const float* skip   = (const float*)d_in[1];
    const float* n1g    = (const float*)d_in[2];
    const float* n1b    = (const float*)d_in[3];
    const float* w_qkv  = (const float*)d_in[4];
    const float* b_qkv  = (const float*)d_in[5];
    const float* w_skip = (const float*)d_in[6];
    const float* b_skip = (const float*)d_in[7];
    const float* relb   = (const float*)d_in[8];
    const float* w_proj = (const float*)d_in[9];
    const float* b_proj = (const float*)d_in[10];
    const float* n2g    = (const float*)d_in[11];
    const float* n2b    = (const float*)d_in[12];
    const float* w_fc1  = (const float*)d_in[13];
    const float* b_fc1  = (const float*)d_in[14];
    const float* w_fc2  = (const float*)d_in[15];
    const float* b_fc2  = (const float*)d_in[16];
    float* outp = (float*)d_out;

    __half *axA, *asA, *hA, *wqB, *wsB, *wpB, *w1B, *w2B, *kvb, *qb;
    float *xres;
    cudaGetSymbolAddress((void**)&axA, g_axA);
    cudaGetSymbolAddress((void**)&asA, g_asA);
    cudaGetSymbolAddress((void**)&kvb, g_kv);
    cudaGetSymbolAddress((void**)&qb,  g_q);
    cudaGetSymbolAddress((void**)&xres, g_xres);
    cudaGetSymbolAddress((void**)&hA,  g_hA);
    cudaGetSymbolAddress((void**)&wqB, g_wqkvB);
    cudaGetSymbolAddress((void**)&wsB, g_wskipB);
    cudaGetSymbolAddress((void**)&wpB, g_wprojB);
    cudaGetSymbolAddress((void**)&w1B, g_wfc1B);
    cudaGetSymbolAddress((void**)&w2B, g_wfc2B);

    cudaFuncSetAttribute(gemm_h<0>, cudaFuncAttributeMaxDynamicSharedMemorySize, GEMM_SMEM);
    cudaFuncSetAttribute(gemm_h<1>, cudaFuncAttributeMaxDynamicSharedMemorySize, GEMM_SMEM);
    cudaFuncSetAttribute(gemm_h<2>, cudaFuncAttributeMaxDynamicSharedMemorySize, GEMM_SMEM);
    cudaFuncSetAttribute(gemm_h<3>, cudaFuncAttributeMaxDynamicSharedMemorySize, GEMM_SMEM);
    cudaFuncSetAttribute(gemm_h<4>, cudaFuncAttributeMaxDynamicSharedMemorySize, GEMM_SMEM);

    wconvB_kernel<<<(1024*512/8 + 255)/256, 256>>>(w_qkv,  wqB, 512,  1024*512/8);
    wconvB_kernel<<<(512*512/8  + 255)/256, 256>>>(w_skip, wsB, 512,  512*512/8);
    wconvB_kernel<<<(512*512/8  + 255)/256, 256>>>(w_proj, wpB, 512,  512*512/8);
    wconvB_kernel<<<(2048*512/8 + 255)/256, 256>>>(w_fc1,  w1B, 512,  2048*512/8);
    wconvB_kernel<<<(512*2048/8 + 255)/256, 256>>>(w_fc2,  w2B, 2048, 512*2048/8);

    ln1_kernel<<<4096, 512>>>(x, skip, n1g, n1b, axA, asA);
    gemm_h<0><<<dim3(8, 256), 256, GEMM_SMEM>>>(axA, wqB, b_qkv, nullptr, nullptr, kvb, 1024, 512);
    gemm_h<1><<<dim3(4, 256), 256, GEMM_SMEM>>>(asA, wsB, b_skip, nullptr, nullptr, qb, 512, 512);
    attn_kernel<<<dim3(1024, 4), 256>>>(qb, kvb, relb, asA);
    gemm_h<2><<<dim3(4, 256), 256, GEMM_SMEM>>>(asA, wpB, b_proj, xres, x, nullptr, 512, 512);
    ln2_kernel<<<4096, 512>>>(xres, n2g, n2b, axA);
    gemm_h<3><<<dim3(16, 256), 256, GEMM_SMEM>>>(axA, w1B, b_fc1, nullptr, nullptr, hA, 2048, 512);
    gemm_h<4><<<dim3(4, 256), 256, GEMM_SMEM>>>(hA, w2B, b_fc2, outp, xres, nullptr, 512, 2048);
    (void)in_sizes; (void)n_in; (void)out_size;
}

// round 10
// speedup vs baseline: 2.9223x; 1.1000x over previous
#include <cuda_runtime.h>
#include <cuda_fp16.h>
#include <cstdint>

// ---------------------------------------------------------------------------
// SwinBlock sm_103a round 9:
//  - GEMMs: fp16 m16n8k16, 512 threads/CTA (16 warps, 4m x 4n, warp 64x32),
//    CTA 256x128, BK=64, 3-stage cp.async, 1 barrier per k-iter.
//  - Attention (fp16 MMA), LN, wconv: unchanged from round 8.
// ---------------------------------------------------------------------------

#define TOK   65536
#define CEMB  512
#define FFN   2048

__device__ __half g_axA [(size_t)TOK * CEMB];
__device__ __half g_asA [(size_t)TOK * CEMB];
__device__ __half g_kv  [(size_t)TOK * 1024];
__device__ __half g_q   [(size_t)TOK * CEMB];
__device__ float  g_xres[(size_t)TOK * CEMB];
__device__ __half g_hA  [(size_t)TOK * FFN];
__device__ __half g_wqkvB[1024 * 512];
__device__ __half g_wskipB[512 * 512];
__device__ __half g_wprojB[512 * 512];
__device__ __half g_wfc1B[2048 * 512];
__device__ __half g_wfc2B[512 * 2048];

__device__ __forceinline__ int wt_to_nat(int wt) {
    int n   = wt & 63;
    int win = wt >> 6;
    int wi  = win & 63;
    int b   = win >> 6;
    int hp  = ((wi >> 3) << 3) + (n >> 3);
    int wp  = ((wi & 7)  << 3) + (n & 7);
    int h   = (hp + 4) & 63;
    int w   = (wp + 4) & 63;
    return (b << 12) + (h << 6) + w;
}

__device__ __forceinline__ uint32_t pk2(float a, float b) {
    __half2 h = __floats2half2_rn(a, b);
    return *(uint32_t*)&h;
}

__device__ __forceinline__ void mma16(float c[4], const uint32_t a[4],
                                      uint32_t b0, uint32_t b1) {
    asm volatile(
        "mma.sync.aligned.m16n8k16.row.col.f32.f16.f16.f32 "
        "{%0,%1,%2,%3}, {%4,%5,%6,%7}, {%8,%9}, {%0,%1,%2,%3};\n"
        : "+f"(c[0]), "+f"(c[1]), "+f"(c[2]), "+f"(c[3])
        : "r"(a[0]), "r"(a[1]), "r"(a[2]), "r"(a[3]), "r"(b0), "r"(b1));
}

__device__ __forceinline__ void cpa16(uint32_t dst, const void* src) {
    asm volatile("cp.async.cg.shared.global [%0], [%1], 16;\n" :: "r"(dst), "l"(src));
}
__device__ __forceinline__ void cpa_commit() { asm volatile("cp.async.commit_group;\n"); }
__device__ __forceinline__ void cpa_wait1()  { asm volatile("cp.async.wait_group 1;\n"); }
__device__ __forceinline__ void cpa_wait0()  { asm volatile("cp.async.wait_group 0;\n"); }

// ---------------------------------------------------------------------------
// LayerNorm -> f32 smem staging -> fp16 A-layout write.
// ---------------------------------------------------------------------------
__device__ __forceinline__ void ln_row_st(const float* __restrict__ in,
                                          const float* __restrict__ g,
                                          const float* __restrict__ b,
                                          float* __restrict__ stgrow, int lane) {
    float4 v[4];
    float s = 0.f, sq = 0.f;
#pragma unroll
    for (int j = 0; j < 4; j++) {
        v[j] = *(const float4*)(in + (((j << 5) + lane) << 2));
        s  += v[j].x + v[j].y + v[j].z + v[j].w;
        sq += v[j].x*v[j].x + v[j].y*v[j].y + v[j].z*v[j].z + v[j].w*v[j].w;
    }
#pragma unroll
    for (int o = 16; o; o >>= 1) {
        s  += __shfl_xor_sync(0xffffffffu, s, o);
        sq += __shfl_xor_sync(0xffffffffu, sq, o);
    }
    float mean = s * (1.f / 512.f);
    float var  = sq * (1.f / 512.f) - mean * mean;
    float rstd = rsqrtf(var + 1e-5f);
#pragma unroll
    for (int j = 0; j < 4; j++) {
        int off = (((j << 5) + lane) << 2);
        float4 gg = *(const float4*)(g + off);
        float4 bb = *(const float4*)(b + off);
        stgrow[off + 0] = (v[j].x - mean) * rstd * gg.x + bb.x;
        stgrow[off + 1] = (v[j].y - mean) * rstd * gg.y + bb.y;
        stgrow[off + 2] = (v[j].z - mean) * rstd * gg.z + bb.z;
        stgrow[off + 3] = (v[j].w - mean) * rstd * gg.w + bb.w;
    }
}

__device__ __forceinline__ void stg_writeA16(__half* __restrict__ out, int row0,
                                             const float (*stg)[516]) {
    size_t base = (size_t)(row0 >> 7) * (128 * 512) + (size_t)((row0 >> 4) & 7) * 256;
#pragma unroll
    for (int i = 0; i < 2; i++) {
        int f4  = threadIdx.x + (i << 9);
        int kb16 = f4 >> 5;
        int lane = f4 & 31;
        int lr = lane >> 2, tq = lane & 3;
        int c0 = (kb16 << 4) + (tq << 1);
        uint4 o;
        o.x = pk2(stg[lr    ][c0    ], stg[lr    ][c0 + 1]);
        o.y = pk2(stg[lr + 8][c0    ], stg[lr + 8][c0 + 1]);
        o.z = pk2(stg[lr    ][c0 + 8], stg[lr    ][c0 + 9]);
        o.w = pk2(stg[lr + 8][c0 + 8], stg[lr + 8][c0 + 9]);
        *(uint4*)(out + base + (size_t)kb16 * 2048 + lane * 8) = o;
    }
}

__global__ __launch_bounds__(512) void ln1_kernel(const float* __restrict__ x,
                                                  const float* __restrict__ skip,
                                                  const float* __restrict__ g1,
                                                  const float* __restrict__ b1,
                                                  __half* __restrict__ outxA,
                                                  __half* __restrict__ outsA) {
    __shared__ float stg[16][516];
    int warp = threadIdx.x >> 5, lane = threadIdx.x & 31;
    int row0 = blockIdx.x << 4;
    int nat  = wt_to_nat(row0 + warp);
    ln_row_st(x + (size_t)nat * CEMB, g1, b1, stg[warp], lane);
    __syncthreads();
    stg_writeA16(outxA, row0, stg);
    __syncthreads();
    ln_row_st(skip + (size_t)nat * CEMB, g1, b1, stg[warp], lane);
    __syncthreads();
    stg_writeA16(outsA, row0, stg);
}

__global__ __launch_bounds__(512) void ln2_kernel(const float* __restrict__ xin,
                                                  const float* __restrict__ g2,
                                                  const float* __restrict__ b2,
                                                  __half* __restrict__ outA) {
    __shared__ float stg[16][516];
    int warp = threadIdx.x >> 5, lane = threadIdx.x & 31;
    int row0 = blockIdx.x << 4;
    ln_row_st(xin + (size_t)(row0 + warp) * CEMB, g2, b2, stg[warp], lane);
    __syncthreads();
    stg_writeA16(outA, row0, stg);
}

__global__ __launch_bounds__(256) void wconvB_kernel(const float* __restrict__ w,
                                                     __half* __restrict__ out,
                                                     int K, int n8cnt) {
    int id = blockIdx.x * 256 + threadIdx.x;
    if (id >= n8cnt) return;
    size_t p0 = (size_t)id << 3;
    int tp   = K << 7;
    int tile = (int)(p0 / tp);
    int rem  = (int)(p0 - (size_t)tile * tp);
    int kb16 = rem >> 11;
    int rem2 = rem & 2047;
    int ngrp = rem2 >> 8;
    int lane = (rem2 & 255) >> 3;
    int g = lane >> 2, tq = lane & 3;
    int n = (tile << 7) + (ngrp << 4) + g;
    int k = (kb16 << 4) + (tq << 1);
    uint4 o;
    o.x = pk2(w[(size_t)n * K + k],       w[(size_t)n * K + k + 1]);
    o.y = pk2(w[(size_t)n * K + k + 8],   w[(size_t)n * K + k + 9]);
    o.z = pk2(w[(size_t)(n + 8) * K + k],     w[(size_t)(n + 8) * K + k + 1]);
    o.w = pk2(w[(size_t)(n + 8) * K + k + 8], w[(size_t)(n + 8) * K + k + 9]);
    *(uint4*)(out + p0) = o;
}

// ---------------------------------------------------------------------------
// GEMM fp16, 512 threads, 16 warps (4m x 4n), warp 64x32, BK=64, 3 stages.
// EPI: 0 +bias->half nat | 1 (+bias)*scale->half nat
//    | 2 +res scatter f32 nat | 3 gelu->A-layout | 4 +res f32
// ---------------------------------------------------------------------------
#define STG_BYTES 49152
#define GEMM_SMEM (3 * STG_BYTES)

template <int EPI>
__global__ __launch_bounds__(512, 1) void gemm_h(const __half* __restrict__ A,
                                                 const __half* __restrict__ W,
                                                 const float* __restrict__ bias,
                                                 float* __restrict__ out,
                                                 const float* __restrict__ res,
                                                 __half* __restrict__ outh,
                                                 int N, int K) {
    extern __shared__ __align__(16) char smem[];
    const uint32_t sb = (uint32_t)__cvta_generic_to_shared(smem);
    const int tid  = threadIdx.x;
    const int warp = tid >> 5, lane = tid & 31;
    const int wm   = warp >> 2;           // 0..3: 64-row band
    const int wn2  = warp & 3;            // 0..3: 32-col band
    const int g    = lane >> 2, tq = lane & 3;
    const int bm   = blockIdx.y * 256;
    const int bn   = blockIdx.x * 128;

    const size_t aTile = (size_t)(bm >> 7) * 128 * K;
    const size_t bTile = (size_t)(bn >> 7) * 128 * K;

    float acc[4][4][4];
#pragma unroll
    for (int i = 0; i < 4; i++)
#pragma unroll
        for (int j = 0; j < 4; j++)
#pragma unroll
            for (int l = 0; l < 4; l++) acc[i][j][l] = 0.f;

    auto load_stage = [&](int s, int kb) {
        const uint32_t dst = sb + (uint32_t)s * STG_BYTES;
        const size_t ko = (size_t)kb * 8192;
#pragma unroll
        for (int j = 0; j < 4; j++) {          // A: 2048 x 16B
            int f4 = tid + (j << 9);
            int tile = f4 >> 10;
            int rem  = f4 & 1023;
            cpa16(dst + (uint32_t)f4 * 16,
                  A + aTile + (size_t)tile * 128 * K + ko + ((size_t)rem << 3));
        }
#pragma unroll
        for (int j = 0; j < 2; j++) {          // B: 1024 x 16B
            int f4 = tid + (j << 9);
            cpa16(dst + 32768 + (uint32_t)f4 * 16, W + bTile + ko + ((size_t)f4 << 3));
        }
    };

    const int nkb = K >> 6;
    load_stage(0, 0); cpa_commit();
    load_stage(1, 1); cpa_commit();

    const uint32_t aOffW = ((uint32_t)(wm >> 1)) * 16384 + ((wm & 1) * 4) * 512 + lane * 16;
    const uint32_t bOffW = 32768 + (uint32_t)(wn2 * 2) * 512 + lane * 16;

    int stage = 0;
    for (int kb = 0; kb < nkb; kb++) {
        cpa_wait1();
        __syncthreads();
        // issue next-next stage load immediately (its buffer freed last iter)
        if (kb + 2 < nkb) {
            int ns = stage + 2; if (ns >= 3) ns -= 3;
            load_stage(ns, kb + 2);
        }
        cpa_commit();

        const char* st = smem + (size_t)stage * STG_BYTES;
#pragma unroll
        for (int kl = 0; kl < 4; kl++) {
            uint4 a[4], b[2];
#pragma unroll
            for (int mi = 0; mi < 4; mi++)
                a[mi] = *(const uint4*)(st + aOffW + kl * 4096 + mi * 512);
#pragma unroll
            for (int nj = 0; nj < 2; nj++)
                b[nj] = *(const uint4*)(st + bOffW + kl * 4096 + nj * 512);
#pragma unroll
            for (int mi = 0; mi < 4; mi++) {
                uint32_t ar[4] = {a[mi].x, a[mi].y, a[mi].z, a[mi].w};
#pragma unroll
                for (int nj = 0; nj < 2; nj++) {
                    mma16(acc[mi][2 * nj],     ar, b[nj].x, b[nj].y);
                    mma16(acc[mi][2 * nj + 1], ar, b[nj].z, b[nj].w);
                }
            }
        }
        stage++; if (stage >= 3) stage = 0;
    }

    if (EPI == 3) {
        cpa_wait0();
        __syncthreads();
        float* stg = (float*)smem;   // [128][132]
#pragma unroll
        for (int half = 0; half < 2; half++) {
            if ((wm >> 1) == half) {
                const int lrb = (wm & 1) * 64;
#pragma unroll
                for (int mi = 0; mi < 4; mi++)
#pragma unroll
                    for (int n8 = 0; n8 < 4; n8++) {
                        int lc = wn2 * 32 + n8 * 8 + (tq << 1);
                        float bv0 = bias[bn + lc], bv1 = bias[bn + lc + 1];
#pragma unroll
                        for (int hr = 0; hr < 2; hr++) {
                            int lr = lrb + mi * 16 + g + hr * 8;
                            float v0 = acc[mi][n8][hr * 2]     + bv0;
                            float v1 = acc[mi][n8][hr * 2 + 1] + bv1;
                            const float is2 = 0.70710678118654752f;
                            stg[lr * 132 + lc]     = 0.5f * v0 * (1.f + erff(v0 * is2));
                            stg[lr * 132 + lc + 1] = 0.5f * v1 * (1.f + erff(v1 * is2));
                        }
                    }
            }
            __syncthreads();
            size_t tbase = (size_t)((bm >> 7) + half) * 128 * N;
#pragma unroll
            for (int i = 0; i < 4; i++) {
                int f4   = tid + (i << 9);
                int kb16L = f4 >> 8;
                int grp  = (f4 >> 5) & 7;
                int ln2  = f4 & 31;
                int lr   = (grp << 4) + (ln2 >> 2);
                int c0   = (kb16L << 4) + ((ln2 & 3) << 1);
                uint4 o;
                o.x = pk2(stg[lr * 132 + c0],           stg[lr * 132 + c0 + 1]);
                o.y = pk2(stg[(lr + 8) * 132 + c0],     stg[(lr + 8) * 132 + c0 + 1]);
                o.z = pk2(stg[lr * 132 + c0 + 8],       stg[lr * 132 + c0 + 9]);
                o.w = pk2(stg[(lr + 8) * 132 + c0 + 8], stg[(lr + 8) * 132 + c0 + 9]);
                *(uint4*)(outh + tbase + (size_t)((bn >> 4) + kb16L) * 2048
                          + (size_t)grp * 256 + ln2 * 8) = o;
            }
            __syncthreads();
        }
        return;
    }

#pragma unroll
    for (int mi = 0; mi < 4; mi++) {
#pragma unroll
        for (int hr = 0; hr < 2; hr++) {
            int r = bm + wm * 64 + mi * 16 + g + hr * 8;
            size_t obase;
            if (EPI == 2) obase = (size_t)wt_to_nat(r) * CEMB;
            else          obase = (size_t)r * N;
#pragma unroll
            for (int n8 = 0; n8 < 4; n8++) {
                int c = bn + wn2 * 32 + n8 * 8 + (tq << 1);
                float v0 = acc[mi][n8][hr * 2]     + bias[c];
                float v1 = acc[mi][n8][hr * 2 + 1] + bias[c + 1];
                if (EPI == 0) {
                    *(uint32_t*)(outh + obase + c) = pk2(v0, v1);
                } else if (EPI == 1) {
                    const float sc = 0.17677669529663687f;
                    *(uint32_t*)(outh + obase + c) = pk2(v0 * sc, v1 * sc);
                } else {
                    v0 += res[obase + c];
                    v1 += res[obase + c + 1];
                    *(float2*)(out + obase + c) = make_float2(v0, v1);
                }
            }
        }
    }
}

// ---------------------------------------------------------------------------
// Windowed attention via fp16 MMA (unchanged from round 8).
// ---------------------------------------------------------------------------
__global__ __launch_bounds__(256) void attn_kernel(const __half* __restrict__ q,
                                                   const __half* __restrict__ kv,
                                                   const float* __restrict__ rb,
                                                   __half* __restrict__ outA) {
    __shared__ __align__(16) __half sqh[64][40];
    __shared__ __align__(16) __half skh[64][40];
    __shared__ __align__(16) __half svT[32][40];
    __shared__ __align__(16) __half svT2[32][40];
    __shared__ float  sc[64][65];
    __shared__ __half sp[64][40];
    __shared__ __half sp2[64][40];
    __shared__ float  so[64][33];

    const int tid  = threadIdx.x;
    const int warp = tid >> 5, lane = tid & 31;
    const int g    = lane >> 2, tq = lane & 3;
    const int wm   = warp >> 1;
    const int wn   = warp & 1;
    const int win  = blockIdx.x;
    const int wi   = win & 63;
    const int wr   = wi >> 3, wc = wi & 7;
    const int base = win << 6;
    const int h0   = blockIdx.y << 2;
    const size_t tbase = (size_t)(win >> 1) * (128 * 512);
    const int grpBase = (win & 1) * 4;

    for (int h = h0; h < h0 + 4; h++) {
        {
            int rown = tid >> 2;
            int ch   = tid & 3;
            *(uint4*)&sqh[rown][ch << 3] =
                *(const uint4*)(q  + (size_t)(base + rown) * 512  + h * 32 + (ch << 3));
            *(uint4*)&skh[rown][ch << 3] =
                *(const uint4*)(kv + (size_t)(base + rown) * 1024 + h * 32 + (ch << 3));
            const __half* vsrc = kv + (size_t)(base + rown) * 1024 + 512 + h * 32;
#pragma unroll
            for (int dd = 0; dd < 8; dd += 1) {
                int d = (ch << 3) + dd;
                __half vv = vsrc[d];
                if (rown < 32) svT [d][rown]      = vv;
                else           svT2[d][rown - 32] = vv;
            }
        }
        __syncthreads();

        {
            const int tn0 = wm << 4;
            const int n00 = wn << 5;
            uint32_t aF[2][4];
#pragma unroll
            for (int ks = 0; ks < 2; ks++) {
                int k0 = ks << 4;
                aF[ks][0] = *(const uint32_t*)&sqh[tn0 + g    ][(tq << 1) + k0];
                aF[ks][1] = *(const uint32_t*)&sqh[tn0 + g + 8][(tq << 1) + k0];
                aF[ks][2] = *(const uint32_t*)&sqh[tn0 + g    ][(tq << 1) + 8 + k0];
                aF[ks][3] = *(const uint32_t*)&sqh[tn0 + g + 8][(tq << 1) + 8 + k0];
            }
            float accS[4][4];
#pragma unroll
            for (int nj = 0; nj < 4; nj++) {
#pragma unroll
                for (int l = 0; l < 4; l++) accS[nj][l] = 0.f;
#pragma unroll
                for (int ks = 0; ks < 2; ks++) {
                    int k0 = ks << 4;
                    uint32_t b0 = *(const uint32_t*)&skh[n00 + (nj << 3) + g][(tq << 1) + k0];
                    uint32_t b1 = *(const uint32_t*)&skh[n00 + (nj << 3) + g][(tq << 1) + 8 + k0];
                    mma16(accS[nj], aF[ks], b0, b1);
                }
            }
#pragma unroll
            for (int nj = 0; nj < 4; nj++) {
#pragma unroll
                for (int hr = 0; hr < 2; hr++) {
                    int n = tn0 + g + (hr << 3);
                    int cn = 15 * (n >> 3) + (n & 7);
                    int rhn = (wr == 7) ? (((n >> 3) < 4) ? 1 : 2) : 0;
                    int rwn = (wc == 7) ? (((n & 7)  < 4) ? 1 : 2) : 0;
                    int regn = rhn * 3 + rwn;
#pragma unroll
                    for (int cc = 0; cc < 2; cc++) {
                        int m = n00 + (nj << 3) + (tq << 1) + cc;
                        int m2 = 63 - m;
                        int cm = 15 * (m2 >> 3) + (m2 & 7);
                        float bv = rb[(cn + cm) * 16 + h];
                        int rhm = (wr == 7) ? (((m >> 3) < 4) ? 1 : 2) : 0;
                        int rwm = (wc == 7) ? (((m & 7)  < 4) ? 1 : 2) : 0;
                        float msk = ((rhm * 3 + rwm) != regn) ? -100.f : 0.f;
                        sc[n][m] = accS[nj][hr * 2 + cc] + bv + msk;
                    }
                }
            }
        }
        __syncthreads();

        {
            int row = tid >> 2, sub = tid & 3;
            float mx = -1e30f;
#pragma unroll
            for (int j = 0; j < 16; j++) mx = fmaxf(mx, sc[row][sub + 4 * j]);
            mx = fmaxf(mx, __shfl_xor_sync(0xffffffffu, mx, 1));
            mx = fmaxf(mx, __shfl_xor_sync(0xffffffffu, mx, 2));
            float ev[16], sm = 0.f;
#pragma unroll
            for (int j = 0; j < 16; j++) {
                ev[j] = expf(sc[row][sub + 4 * j] - mx);
                sm += ev[j];
            }
            sm += __shfl_xor_sync(0xffffffffu, sm, 1);
            sm += __shfl_xor_sync(0xffffffffu, sm, 2);
            float inv = 1.f / sm;
#pragma unroll
            for (int j = 0; j < 16; j++) {
                int col = sub + 4 * j;
                __half hv = __float2half_rn(ev[j] * inv);
                if (col < 32) sp [row][col]      = hv;
                else          sp2[row][col - 32] = hv;
            }
        }
        __syncthreads();

        {
            const int r0 = wm << 4;
            const int d0 = wn << 4;
            float accO[2][4];
#pragma unroll
            for (int nj = 0; nj < 2; nj++)
#pragma unroll
                for (int l = 0; l < 4; l++) accO[nj][l] = 0.f;
#pragma unroll
            for (int kk = 0; kk < 4; kk++) {
                int k0 = (kk & 1) << 4;
                const __half (*spp)[40] = (kk < 2) ? sp  : sp2;
                const __half (*svv)[40] = (kk < 2) ? svT : svT2;
                uint32_t aP[4];
                aP[0] = *(const uint32_t*)&spp[r0 + g    ][(tq << 1) + k0];
                aP[1] = *(const uint32_t*)&spp[r0 + g + 8][(tq << 1) + k0];
                aP[2] = *(const uint32_t*)&spp[r0 + g    ][(tq << 1) + 8 + k0];
                aP[3] = *(const uint32_t*)&spp[r0 + g + 8][(tq << 1) + 8 + k0];
#pragma unroll
                for (int nj = 0; nj < 2; nj++) {
                    uint32_t b0 = *(const uint32_t*)&svv[d0 + (nj << 3) + g][(tq << 1) + k0];
                    uint32_t b1 = *(const uint32_t*)&svv[d0 + (nj << 3) + g][(tq << 1) + 8 + k0];
                    mma16(accO[nj], aP, b0, b1);
                }
            }
#pragma unroll
            for (int nj = 0; nj < 2; nj++)
#pragma unroll
                for (int hr = 0; hr < 2; hr++) {
                    int rr = r0 + g + (hr << 3);
                    int dd = d0 + (nj << 3) + (tq << 1);
                    so[rr][dd]     = accO[nj][hr * 2];
                    so[rr][dd + 1] = accO[nj][hr * 2 + 1];
                }
        }
        __syncthreads();

        {
            int kb16L = tid >> 7;
            int grpL  = (tid >> 5) & 3;
            int ln2   = tid & 31;
            int lr    = (grpL << 4) + (ln2 >> 2);
            int c0    = (kb16L << 4) + ((ln2 & 3) << 1);
            uint4 o;
            o.x = pk2(so[lr][c0],         so[lr][c0 + 1]);
            o.y = pk2(so[lr + 8][c0],     so[lr + 8][c0 + 1]);
            o.z = pk2(so[lr][c0 + 8],     so[lr][c0 + 9]);
            o.w = pk2(so[lr + 8][c0 + 8], so[lr + 8][c0 + 9]);
            *(uint4*)(outA + tbase + (size_t)(2 * h + kb16L) * 2048
                      + (size_t)(grpBase + grpL) * 256 + ln2 * 8) = o;
        }
        __syncthreads();
    }
}

// ---------------------------------------------------------------------------
extern "C" void kernel_launch(void* const* d_in, const int* in_sizes, int n_in,
                              void* d_out, int out_size) {
    const float* x      = (const float*)d_in[0];
    const float* skip   = (const float*)d_in[1];
    const float* n1g    = (const float*)d_in[2];
    const float* n1b    = (const float*)d_in[3];
    const float* w_qkv  = (const float*)d_in[4];
    const float* b_qkv  = (const float*)d_in[5];
    const float* w_skip = (const float*)d_in[6];
    const float* b_skip = (const float*)d_in[7];
    const float* relb   = (const float*)d_in[8];
    const float* w_proj = (const float*)d_in[9];
    const float* b_proj = (const float*)d_in[10];
    const float* n2g    = (const float*)d_in[11];
    const float* n2b    = (const float*)d_in[12];
    const float* w_fc1  = (const float*)d_in[13];
    const float* b_fc1  = (const float*)d_in[14];
    const float* w_fc2  = (const float*)d_in[15];
    const float* b_fc2  = (const float*)d_in[16];
    float* outp = (float*)d_out;

    __half *axA, *asA, *hA, *wqB, *wsB, *wpB, *w1B, *w2B, *kvb, *qb;
    float *xres;
    cudaGetSymbolAddress((void**)&axA, g_axA);
    cudaGetSymbolAddress((void**)&asA, g_asA);
    cudaGetSymbolAddress((void**)&kvb, g_kv);
    cudaGetSymbolAddress((void**)&qb,  g_q);
    cudaGetSymbolAddress((void**)&xres, g_xres);
    cudaGetSymbolAddress((void**)&hA,  g_hA);
    cudaGetSymbolAddress((void**)&wqB, g_wqkvB);
    cudaGetSymbolAddress((void**)&wsB, g_wskipB);
    cudaGetSymbolAddress((void**)&wpB, g_wprojB);
    cudaGetSymbolAddress((void**)&w1B, g_wfc1B);
    cudaGetSymbolAddress((void**)&w2B, g_wfc2B);

    cudaFuncSetAttribute(gemm_h<0>, cudaFuncAttributeMaxDynamicSharedMemorySize, GEMM_SMEM);
    cudaFuncSetAttribute(gemm_h<1>, cudaFuncAttributeMaxDynamicSharedMemorySize, GEMM_SMEM);
    cudaFuncSetAttribute(gemm_h<2>, cudaFuncAttributeMaxDynamicSharedMemorySize, GEMM_SMEM);
    cudaFuncSetAttribute(gemm_h<3>, cudaFuncAttributeMaxDynamicSharedMemorySize, GEMM_SMEM);
    cudaFuncSetAttribute(gemm_h<4>, cudaFuncAttributeMaxDynamicSharedMemorySize, GEMM_SMEM);

    wconvB_kernel<<<(1024*512/8 + 255)/256, 256>>>(w_qkv,  wqB, 512,  1024*512/8);
    wconvB_kernel<<<(512*512/8  + 255)/256, 256>>>(w_skip, wsB, 512,  512*512/8);
    wconvB_kernel<<<(512*512/8  + 255)/256, 256>>>(w_proj, wpB, 512,  512*512/8);
    wconvB_kernel<<<(2048*512/8 + 255)/256, 256>>>(w_fc1,  w1B, 512,  2048*512/8);
    wconvB_kernel<<<(512*2048/8 + 255)/256, 256>>>(w_fc2,  w2B, 2048, 512*2048/8);

    ln1_kernel<<<4096, 512>>>(x, skip, n1g, n1b, axA, asA);
    gemm_h<0><<<dim3(8, 256), 512, GEMM_SMEM>>>(axA, wqB, b_qkv, nullptr, nullptr, kvb, 1024, 512);
    gemm_h<1><<<dim3(4, 256), 512, GEMM_SMEM>>>(asA, wsB, b_skip, nullptr, nullptr, qb, 512, 512);
    attn_kernel<<<dim3(1024, 4), 256>>>(qb, kvb, relb, asA);
    gemm_h<2><<<dim3(4, 256), 512, GEMM_SMEM>>>(asA, wpB, b_proj, xres, x, nullptr, 512, 512);
    ln2_kernel<<<4096, 512>>>(xres, n2g, n2b, axA);
    gemm_h<3><<<dim3(16, 256), 512, GEMM_SMEM>>>(axA, w1B, b_fc1, nullptr, nullptr, hA, 2048, 512);
    gemm_h<4><<<dim3(4, 256), 512, GEMM_SMEM>>>(hA, w2B, b_fc2, outp, xres, nullptr, 512, 2048);
    (void)in_sizes; (void)n_in; (void)out_size;
}

// round 11
// speedup vs baseline: 3.0919x; 1.0580x over previous
#include <cuda_runtime.h>
#include <cuda_fp16.h>
#include <cstdint>

// ---------------------------------------------------------------------------
// SwinBlock sm_103a round 10:
//  - GEMMs/LN: unchanged from round 9 (fp16 m16n8k16, 512thr, 3-stage).
//  - Attention: flash-style register-resident P (C-frag == A-frag identity),
//    two-level softmax, cross-warp O partial sum. 4 barriers/head, no sc/sp.
//  - wconv: 5 launches merged into 1.
// ---------------------------------------------------------------------------

#define TOK   65536
#define CEMB  512
#define FFN   2048

__device__ __half g_axA [(size_t)TOK * CEMB];
__device__ __half g_asA [(size_t)TOK * CEMB];
__device__ __half g_kv  [(size_t)TOK * 1024];
__device__ __half g_q   [(size_t)TOK * CEMB];
__device__ float  g_xres[(size_t)TOK * CEMB];
__device__ __half g_hA  [(size_t)TOK * FFN];
__device__ __half g_wqkvB[1024 * 512];
__device__ __half g_wskipB[512 * 512];
__device__ __half g_wprojB[512 * 512];
__device__ __half g_wfc1B[2048 * 512];
__device__ __half g_wfc2B[512 * 2048];

__device__ __forceinline__ int wt_to_nat(int wt) {
    int n   = wt & 63;
    int win = wt >> 6;
    int wi  = win & 63;
    int b   = win >> 6;
    int hp  = ((wi >> 3) << 3) + (n >> 3);
    int wp  = ((wi & 7)  << 3) + (n & 7);
    int h   = (hp + 4) & 63;
    int w   = (wp + 4) & 63;
    return (b << 12) + (h << 6) + w;
}

__device__ __forceinline__ uint32_t pk2(float a, float b) {
    __half2 h = __floats2half2_rn(a, b);
    return *(uint32_t*)&h;
}

__device__ __forceinline__ void mma16(float c[4], const uint32_t a[4],
                                      uint32_t b0, uint32_t b1) {
    asm volatile(
        "mma.sync.aligned.m16n8k16.row.col.f32.f16.f16.f32 "
        "{%0,%1,%2,%3}, {%4,%5,%6,%7}, {%8,%9}, {%0,%1,%2,%3};\n"
        : "+f"(c[0]), "+f"(c[1]), "+f"(c[2]), "+f"(c[3])
        : "r"(a[0]), "r"(a[1]), "r"(a[2]), "r"(a[3]), "r"(b0), "r"(b1));
}

__device__ __forceinline__ void cpa16(uint32_t dst, const void* src) {
    asm volatile("cp.async.cg.shared.global [%0], [%1], 16;\n" :: "r"(dst), "l"(src));
}
__device__ __forceinline__ void cpa_commit() { asm volatile("cp.async.commit_group;\n"); }
__device__ __forceinline__ void cpa_wait1()  { asm volatile("cp.async.wait_group 1;\n"); }
__device__ __forceinline__ void cpa_wait0()  { asm volatile("cp.async.wait_group 0;\n"); }

// ---------------------------------------------------------------------------
// LayerNorm -> f32 smem staging -> fp16 A-layout write. (unchanged)
// ---------------------------------------------------------------------------
__device__ __forceinline__ void ln_row_st(const float* __restrict__ in,
                                          const float* __restrict__ g,
                                          const float* __restrict__ b,
                                          float* __restrict__ stgrow, int lane) {
    float4 v[4];
    float s = 0.f, sq = 0.f;
#pragma unroll
    for (int j = 0; j < 4; j++) {
        v[j] = *(const float4*)(in + (((j << 5) + lane) << 2));
        s  += v[j].x + v[j].y + v[j].z + v[j].w;
        sq += v[j].x*v[j].x + v[j].y*v[j].y + v[j].z*v[j].z + v[j].w*v[j].w;
    }
#pragma unroll
    for (int o = 16; o; o >>= 1) {
        s  += __shfl_xor_sync(0xffffffffu, s, o);
        sq += __shfl_xor_sync(0xffffffffu, sq, o);
    }
    float mean = s * (1.f / 512.f);
    float var  = sq * (1.f / 512.f) - mean * mean;
    float rstd = rsqrtf(var + 1e-5f);
#pragma unroll
    for (int j = 0; j < 4; j++) {
        int off = (((j << 5) + lane) << 2);
        float4 gg = *(const float4*)(g + off);
        float4 bb = *(const float4*)(b + off);
        stgrow[off + 0] = (v[j].x - mean) * rstd * gg.x + bb.x;
        stgrow[off + 1] = (v[j].y - mean) * rstd * gg.y + bb.y;
        stgrow[off + 2] = (v[j].z - mean) * rstd * gg.z + bb.z;
        stgrow[off + 3] = (v[j].w - mean) * rstd * gg.w + bb.w;
    }
}

__device__ __forceinline__ void stg_writeA16(__half* __restrict__ out, int row0,
                                             const float (*stg)[516]) {
    size_t base = (size_t)(row0 >> 7) * (128 * 512) + (size_t)((row0 >> 4) & 7) * 256;
#pragma unroll
    for (int i = 0; i < 2; i++) {
        int f4  = threadIdx.x + (i << 9);
        int kb16 = f4 >> 5;
        int lane = f4 & 31;
        int lr = lane >> 2, tq = lane & 3;
        int c0 = (kb16 << 4) + (tq << 1);
        uint4 o;
        o.x = pk2(stg[lr    ][c0    ], stg[lr    ][c0 + 1]);
        o.y = pk2(stg[lr + 8][c0    ], stg[lr + 8][c0 + 1]);
        o.z = pk2(stg[lr    ][c0 + 8], stg[lr    ][c0 + 9]);
        o.w = pk2(stg[lr + 8][c0 + 8], stg[lr + 8][c0 + 9]);
        *(uint4*)(out + base + (size_t)kb16 * 2048 + lane * 8) = o;
    }
}

__global__ __launch_bounds__(512) void ln1_kernel(const float* __restrict__ x,
                                                  const float* __restrict__ skip,
                                                  const float* __restrict__ g1,
                                                  const float* __restrict__ b1,
                                                  __half* __restrict__ outxA,
                                                  __half* __restrict__ outsA) {
    __shared__ float stg[16][516];
    int warp = threadIdx.x >> 5, lane = threadIdx.x & 31;
    int row0 = blockIdx.x << 4;
    int nat  = wt_to_nat(row0 + warp);
    ln_row_st(x + (size_t)nat * CEMB, g1, b1, stg[warp], lane);
    __syncthreads();
    stg_writeA16(outxA, row0, stg);
    __syncthreads();
    ln_row_st(skip + (size_t)nat * CEMB, g1, b1, stg[warp], lane);
    __syncthreads();
    stg_writeA16(outsA, row0, stg);
}

__global__ __launch_bounds__(512) void ln2_kernel(const float* __restrict__ xin,
                                                  const float* __restrict__ g2,
                                                  const float* __restrict__ b2,
                                                  __half* __restrict__ outA) {
    __shared__ float stg[16][516];
    int warp = threadIdx.x >> 5, lane = threadIdx.x & 31;
    int row0 = blockIdx.x << 4;
    ln_row_st(xin + (size_t)(row0 + warp) * CEMB, g2, b2, stg[warp], lane);
    __syncthreads();
    stg_writeA16(outA, row0, stg);
}

// merged weight converter: one launch for all 5 weights
__global__ __launch_bounds__(256) void wconv_all(const float* __restrict__ w0,
                                                 const float* __restrict__ w1,
                                                 const float* __restrict__ w2,
                                                 const float* __restrict__ w3,
                                                 const float* __restrict__ w4,
                                                 __half* __restrict__ o0,
                                                 __half* __restrict__ o1,
                                                 __half* __restrict__ o2,
                                                 __half* __restrict__ o3,
                                                 __half* __restrict__ o4) {
    int id = blockIdx.x * 256 + threadIdx.x;       // unit = 8 halves
    const float* w; __half* out; int K; int lid;
    if (id < 65536)       { w = w0; out = o0; K = 512;  lid = id; }
    else if (id < 98304)  { w = w1; out = o1; K = 512;  lid = id - 65536; }
    else if (id < 131072) { w = w2; out = o2; K = 512;  lid = id - 98304; }
    else if (id < 262144) { w = w3; out = o3; K = 512;  lid = id - 131072; }
    else                  { w = w4; out = o4; K = 2048; lid = id - 262144; }
    size_t p0 = (size_t)lid << 3;
    int tp   = K << 7;
    int tile = (int)(p0 / tp);
    int rem  = (int)(p0 - (size_t)tile * tp);
    int kb16 = rem >> 11;
    int rem2 = rem & 2047;
    int ngrp = rem2 >> 8;
    int lane = (rem2 & 255) >> 3;
    int g = lane >> 2, tq = lane & 3;
    int n = (tile << 7) + (ngrp << 4) + g;
    int k = (kb16 << 4) + (tq << 1);
    uint4 o;
    o.x = pk2(w[(size_t)n * K + k],       w[(size_t)n * K + k + 1]);
    o.y = pk2(w[(size_t)n * K + k + 8],   w[(size_t)n * K + k + 9]);
    o.z = pk2(w[(size_t)(n + 8) * K + k],     w[(size_t)(n + 8) * K + k + 1]);
    o.w = pk2(w[(size_t)(n + 8) * K + k + 8], w[(size_t)(n + 8) * K + k + 9]);
    *(uint4*)(out + p0) = o;
}

// ---------------------------------------------------------------------------
// GEMM fp16, 512 threads, 16 warps (4m x 4n), warp 64x32, BK=64, 3 stages.
// (unchanged from round 9)
// ---------------------------------------------------------------------------
#define STG_BYTES 49152
#define GEMM_SMEM (3 * STG_BYTES)

template <int EPI>
__global__ __launch_bounds__(512, 1) void gemm_h(const __half* __restrict__ A,
                                                 const __half* __restrict__ W,
                                                 const float* __restrict__ bias,
                                                 float* __restrict__ out,
                                                 const float* __restrict__ res,
                                                 __half* __restrict__ outh,
                                                 int N, int K) {
    extern __shared__ __align__(16) char smem[];
    const uint32_t sb = (uint32_t)__cvta_generic_to_shared(smem);
    const int tid  = threadIdx.x;
    const int warp = tid >> 5, lane = tid & 31;
    const int wm   = warp >> 2;
    const int wn2  = warp & 3;
    const int g    = lane >> 2, tq = lane & 3;
    const int bm   = blockIdx.y * 256;
    const int bn   = blockIdx.x * 128;

    const size_t aTile = (size_t)(bm >> 7) * 128 * K;
    const size_t bTile = (size_t)(bn >> 7) * 128 * K;

    float acc[4][4][4];
#pragma unroll
    for (int i = 0; i < 4; i++)
#pragma unroll
        for (int j = 0; j < 4; j++)
#pragma unroll
            for (int l = 0; l < 4; l++) acc[i][j][l] = 0.f;

    auto load_stage = [&](int s, int kb) {
        const uint32_t dst = sb + (uint32_t)s * STG_BYTES;
        const size_t ko = (size_t)kb * 8192;
#pragma unroll
        for (int j = 0; j < 4; j++) {
            int f4 = tid + (j << 9);
            int tile = f4 >> 10;
            int rem  = f4 & 1023;
            cpa16(dst + (uint32_t)f4 * 16,
                  A + aTile + (size_t)tile * 128 * K + ko + ((size_t)rem << 3));
        }
#pragma unroll
        for (int j = 0; j < 2; j++) {
            int f4 = tid + (j << 9);
            cpa16(dst + 32768 + (uint32_t)f4 * 16, W + bTile + ko + ((size_t)f4 << 3));
        }
    };

    const int nkb = K >> 6;
    load_stage(0, 0); cpa_commit();
    load_stage(1, 1); cpa_commit();

    const uint32_t aOffW = ((uint32_t)(wm >> 1)) * 16384 + ((wm & 1) * 4) * 512 + lane * 16;
    const uint32_t bOffW = 32768 + (uint32_t)(wn2 * 2) * 512 + lane * 16;

    int stage = 0;
    for (int kb = 0; kb < nkb; kb++) {
        cpa_wait1();
        __syncthreads();
        if (kb + 2 < nkb) {
            int ns = stage + 2; if (ns >= 3) ns -= 3;
            load_stage(ns, kb + 2);
        }
        cpa_commit();

        const char* st = smem + (size_t)stage * STG_BYTES;
#pragma unroll
        for (int kl = 0; kl < 4; kl++) {
            uint4 a[4], b[2];
#pragma unroll
            for (int mi = 0; mi < 4; mi++)
                a[mi] = *(const uint4*)(st + aOffW + kl * 4096 + mi * 512);
#pragma unroll
            for (int nj = 0; nj < 2; nj++)
                b[nj] = *(const uint4*)(st + bOffW + kl * 4096 + nj * 512);
#pragma unroll
            for (int mi = 0; mi < 4; mi++) {
                uint32_t ar[4] = {a[mi].x, a[mi].y, a[mi].z, a[mi].w};
#pragma unroll
                for (int nj = 0; nj < 2; nj++) {
                    mma16(acc[mi][2 * nj],     ar, b[nj].x, b[nj].y);
                    mma16(acc[mi][2 * nj + 1], ar, b[nj].z, b[nj].w);
                }
            }
        }
        stage++; if (stage >= 3) stage = 0;
    }

    if (EPI == 3) {
        cpa_wait0();
        __syncthreads();
        float* stg = (float*)smem;
#pragma unroll
        for (int half = 0; half < 2; half++) {
            if ((wm >> 1) == half) {
                const int lrb = (wm & 1) * 64;
#pragma unroll
                for (int mi = 0; mi < 4; mi++)
#pragma unroll
                    for (int n8 = 0; n8 < 4; n8++) {
                        int lc = wn2 * 32 + n8 * 8 + (tq << 1);
                        float bv0 = bias[bn + lc], bv1 = bias[bn + lc + 1];
#pragma unroll
                        for (int hr = 0; hr < 2; hr++) {
                            int lr = lrb + mi * 16 + g + hr * 8;
                            float v0 = acc[mi][n8][hr * 2]     + bv0;
                            float v1 = acc[mi][n8][hr * 2 + 1] + bv1;
                            const float is2 = 0.70710678118654752f;
                            stg[lr * 132 + lc]     = 0.5f * v0 * (1.f + erff(v0 * is2));
                            stg[lr * 132 + lc + 1] = 0.5f * v1 * (1.f + erff(v1 * is2));
                        }
                    }
            }
            __syncthreads();
            size_t tbase = (size_t)((bm >> 7) + half) * 128 * N;
#pragma unroll
            for (int i = 0; i < 4; i++) {
                int f4   = tid + (i << 9);
                int kb16L = f4 >> 8;
                int grp  = (f4 >> 5) & 7;
                int ln2  = f4 & 31;
                int lr   = (grp << 4) + (ln2 >> 2);
                int c0   = (kb16L << 4) + ((ln2 & 3) << 1);
                uint4 o;
                o.x = pk2(stg[lr * 132 + c0],           stg[lr * 132 + c0 + 1]);
                o.y = pk2(stg[(lr + 8) * 132 + c0],     stg[(lr + 8) * 132 + c0 + 1]);
                o.z = pk2(stg[lr * 132 + c0 + 8],       stg[lr * 132 + c0 + 9]);
                o.w = pk2(stg[(lr + 8) * 132 + c0 + 8], stg[(lr + 8) * 132 + c0 + 9]);
                *(uint4*)(outh + tbase + (size_t)((bn >> 4) + kb16L) * 2048
                          + (size_t)grp * 256 + ln2 * 8) = o;
            }
            __syncthreads();
        }
        return;
    }

#pragma unroll
    for (int mi = 0; mi < 4; mi++) {
#pragma unroll
        for (int hr = 0; hr < 2; hr++) {
            int r = bm + wm * 64 + mi * 16 + g + hr * 8;
            size_t obase;
            if (EPI == 2) obase = (size_t)wt_to_nat(r) * CEMB;
            else          obase = (size_t)r * N;
#pragma unroll
            for (int n8 = 0; n8 < 4; n8++) {
                int c = bn + wn2 * 32 + n8 * 8 + (tq << 1);
                float v0 = acc[mi][n8][hr * 2]     + bias[c];
                float v1 = acc[mi][n8][hr * 2 + 1] + bias[c + 1];
                if (EPI == 0) {
                    *(uint32_t*)(outh + obase + c) = pk2(v0, v1);
                } else if (EPI == 1) {
                    const float sc = 0.17677669529663687f;
                    *(uint32_t*)(outh + obase + c) = pk2(v0 * sc, v1 * sc);
                } else {
                    v0 += res[obase + c];
                    v1 += res[obase + c + 1];
                    *(float2*)(out + obase + c) = make_float2(v0, v1);
                }
            }
        }
    }
}

// ---------------------------------------------------------------------------
// Windowed attention, flash-style: P stays in registers (C-frag -> A-frag).
// Grid (1024 windows, 4 head-groups), 256 threads (8 warps: 4 row-bands x
// 2 key-bands). Two-level softmax; cross-warp O partial sum via smem.
// ---------------------------------------------------------------------------
__global__ __launch_bounds__(256) void attn_kernel(const __half* __restrict__ q,
                                                   const __half* __restrict__ kv,
                                                   const float* __restrict__ rb,
                                                   __half* __restrict__ outA) {
    __shared__ __align__(16) __half sqh[64][40];
    __shared__ __align__(16) __half skh[64][40];
    __shared__ __align__(16) __half svT[32][72];   // V^T: [d][key]
    __shared__ float redm[2][64];
    __shared__ float reds[2][64];
    __shared__ float soP[2][64][36];               // per-key-band O partials

    const int tid  = threadIdx.x;
    const int warp = tid >> 5, lane = tid & 31;
    const int g    = lane >> 2, tq = lane & 3;
    const int wm   = warp >> 1;        // row band (16 rows)
    const int wn   = warp & 1;         // key band (32 keys)
    const int tn0  = wm << 4;
    const int n00  = wn << 5;
    const int win  = blockIdx.x;
    const int wi   = win & 63;
    const int wr   = wi >> 3, wc = wi & 7;
    const int base = win << 6;
    const int h0   = blockIdx.y << 2;
    const size_t tbase = (size_t)(win >> 1) * (128 * 512);
    const int grpBase = (win & 1) * 4;

    for (int h = h0; h < h0 + 4; h++) {
        // ---- load Q, K, V^T
        {
            int rown = tid >> 2;
            int ch   = tid & 3;
            *(uint4*)&sqh[rown][ch << 3] =
                *(const uint4*)(q  + (size_t)(base + rown) * 512  + h * 32 + (ch << 3));
            *(uint4*)&skh[rown][ch << 3] =
                *(const uint4*)(kv + (size_t)(base + rown) * 1024 + h * 32 + (ch << 3));
            union { uint4 u; __half hs[8]; } vv;
            vv.u = *(const uint4*)(kv + (size_t)(base + rown) * 1024 + 512 + h * 32 + (ch << 3));
#pragma unroll
            for (int dd = 0; dd < 8; dd++)
                svT[(ch << 3) + dd][rown] = vv.hs[dd];
        }
        __syncthreads();

        // ---- S = Q K^T (+bias+mask), in registers
        float s[4][4];
        {
            uint32_t aF[2][4];
#pragma unroll
            for (int ks = 0; ks < 2; ks++) {
                int k0 = ks << 4;
                aF[ks][0] = *(const uint32_t*)&sqh[tn0 + g    ][(tq << 1) + k0];
                aF[ks][1] = *(const uint32_t*)&sqh[tn0 + g + 8][(tq << 1) + k0];
                aF[ks][2] = *(const uint32_t*)&sqh[tn0 + g    ][(tq << 1) + 8 + k0];
                aF[ks][3] = *(const uint32_t*)&sqh[tn0 + g + 8][(tq << 1) + 8 + k0];
            }
#pragma unroll
            for (int nj = 0; nj < 4; nj++) {
#pragma unroll
                for (int l = 0; l < 4; l++) s[nj][l] = 0.f;
#pragma unroll
                for (int ks = 0; ks < 2; ks++) {
                    int k0 = ks << 4;
                    uint32_t b0 = *(const uint32_t*)&skh[n00 + (nj << 3) + g][(tq << 1) + k0];
                    uint32_t b1 = *(const uint32_t*)&skh[n00 + (nj << 3) + g][(tq << 1) + 8 + k0];
                    mma16(s[nj], aF[ks], b0, b1);
                }
            }
            // bias + mask in regs
#pragma unroll
            for (int hr = 0; hr < 2; hr++) {
                int n = tn0 + g + (hr << 3);
                int cn = 15 * (n >> 3) + (n & 7);
                int rhn = (wr == 7) ? (((n >> 3) < 4) ? 1 : 2) : 0;
                int rwn = (wc == 7) ? (((n & 7)  < 4) ? 1 : 2) : 0;
                int regn = rhn * 3 + rwn;
#pragma unroll
                for (int nj = 0; nj < 4; nj++)
#pragma unroll
                    for (int cc = 0; cc < 2; cc++) {
                        int m = n00 + (nj << 3) + (tq << 1) + cc;
                        int m2 = 63 - m;
                        int cm = 15 * (m2 >> 3) + (m2 & 7);
                        float bv = rb[(cn + cm) * 16 + h];
                        int rhm = (wr == 7) ? (((m >> 3) < 4) ? 1 : 2) : 0;
                        int rwm = (wc == 7) ? (((m & 7)  < 4) ? 1 : 2) : 0;
                        float msk = ((rhm * 3 + rwm) != regn) ? -100.f : 0.f;
                        s[nj][hr * 2 + cc] += bv + msk;
                    }
            }
        }

        // ---- two-level softmax
        float e[4][4], scl0, scl1;
        {
            float mx0 = -1e30f, mx1 = -1e30f;
#pragma unroll
            for (int nj = 0; nj < 4; nj++) {
                mx0 = fmaxf(mx0, fmaxf(s[nj][0], s[nj][1]));
                mx1 = fmaxf(mx1, fmaxf(s[nj][2], s[nj][3]));
            }
            mx0 = fmaxf(mx0, __shfl_xor_sync(0xffffffffu, mx0, 1));
            mx0 = fmaxf(mx0, __shfl_xor_sync(0xffffffffu, mx0, 2));
            mx1 = fmaxf(mx1, __shfl_xor_sync(0xffffffffu, mx1, 1));
            mx1 = fmaxf(mx1, __shfl_xor_sync(0xffffffffu, mx1, 2));
            float sm0 = 0.f, sm1 = 0.f;
#pragma unroll
            for (int nj = 0; nj < 4; nj++) {
                e[nj][0] = expf(s[nj][0] - mx0);
                e[nj][1] = expf(s[nj][1] - mx0);
                e[nj][2] = expf(s[nj][2] - mx1);
                e[nj][3] = expf(s[nj][3] - mx1);
                sm0 += e[nj][0] + e[nj][1];
                sm1 += e[nj][2] + e[nj][3];
            }
            sm0 += __shfl_xor_sync(0xffffffffu, sm0, 1);
            sm0 += __shfl_xor_sync(0xffffffffu, sm0, 2);
            sm1 += __shfl_xor_sync(0xffffffffu, sm1, 1);
            sm1 += __shfl_xor_sync(0xffffffffu, sm1, 2);
            if (tq == 0) {
                redm[wn][tn0 + g]     = mx0;  reds[wn][tn0 + g]     = sm0;
                redm[wn][tn0 + g + 8] = mx1;  reds[wn][tn0 + g + 8] = sm1;
            }
            __syncthreads();
            int r0 = tn0 + g, r1 = tn0 + g + 8;
            float Ma = fmaxf(redm[0][r0], redm[1][r0]);
            float den0 = reds[0][r0] * expf(redm[0][r0] - Ma)
                       + reds[1][r0] * expf(redm[1][r0] - Ma);
            scl0 = expf(mx0 - Ma) / den0;
            float Mb = fmaxf(redm[0][r1], redm[1][r1]);
            float den1 = reds[0][r1] * expf(redm[0][r1] - Mb)
                       + reds[1][r1] * expf(redm[1][r1] - Mb);
            scl1 = expf(mx1 - Mb) / den1;
        }

        // ---- pack P into A-fragments (C-layout == A-layout identity)
        uint32_t aP[2][4];
#pragma unroll
        for (int kj = 0; kj < 2; kj++) {
            int njl = kj * 2, njh = kj * 2 + 1;
            aP[kj][0] = pk2(e[njl][0] * scl0, e[njl][1] * scl0);
            aP[kj][1] = pk2(e[njl][2] * scl1, e[njl][3] * scl1);
            aP[kj][2] = pk2(e[njh][0] * scl0, e[njh][1] * scl0);
            aP[kj][3] = pk2(e[njh][2] * scl1, e[njh][3] * scl1);
        }

        // ---- O partial = P(band) V(band), all 32 d
        float accO[4][4];
#pragma unroll
        for (int dj = 0; dj < 4; dj++)
#pragma unroll
            for (int l = 0; l < 4; l++) accO[dj][l] = 0.f;
#pragma unroll
        for (int kj = 0; kj < 2; kj++) {
            int kbase = n00 + (kj << 4) + (tq << 1);
#pragma unroll
            for (int dj = 0; dj < 4; dj++) {
                uint32_t b0 = *(const uint32_t*)&svT[(dj << 3) + g][kbase];
                uint32_t b1 = *(const uint32_t*)&svT[(dj << 3) + g][kbase + 8];
                mma16(accO[dj], aP[kj], b0, b1);
            }
        }
#pragma unroll
        for (int dj = 0; dj < 4; dj++)
#pragma unroll
            for (int hr = 0; hr < 2; hr++) {
                int rr = tn0 + g + (hr << 3);
                int dd = (dj << 3) + (tq << 1);
                *(float2*)&soP[wn][rr][dd] =
                    make_float2(accO[dj][hr * 2], accO[dj][hr * 2 + 1]);
            }
        __syncthreads();

        // ---- combine bands + pack fp16 A-layout
        {
            int kb16L = tid >> 7;
            int grpL  = (tid >> 5) & 3;
            int ln2   = tid & 31;
            int lr    = (grpL << 4) + (ln2 >> 2);
            int c0    = (kb16L << 4) + ((ln2 & 3) << 1);
            uint4 o;
            o.x = pk2(soP[0][lr][c0]         + soP[1][lr][c0],
                      soP[0][lr][c0 + 1]     + soP[1][lr][c0 + 1]);
            o.y = pk2(soP[0][lr + 8][c0]     + soP[1][lr + 8][c0],
                      soP[0][lr + 8][c0 + 1] + soP[1][lr + 8][c0 + 1]);
            o.z = pk2(soP[0][lr][c0 + 8]     + soP[1][lr][c0 + 8],
                      soP[0][lr][c0 + 9]     + soP[1][lr][c0 + 9]);
            o.w = pk2(soP[0][lr + 8][c0 + 8] + soP[1][lr + 8][c0 + 8],
                      soP[0][lr + 8][c0 + 9] + soP[1][lr + 8][c0 + 9]);
            *(uint4*)(outA + tbase + (size_t)(2 * h + kb16L) * 2048
                      + (size_t)(grpBase + grpL) * 256 + ln2 * 8) = o;
        }
        __syncthreads();
    }
}

// ---------------------------------------------------------------------------
extern "C" void kernel_launch(void* const* d_in, const int* in_sizes, int n_in,
                              void* d_out, int out_size) {
    const float* x      = (const float*)d_in[0];
    const float* skip   = (const float*)d_in[1];
    const float* n1g    = (const float*)d_in[2];
    const float* n1b    = (const float*)d_in[3];
    const float* w_qkv  = (const float*)d_in[4];
    const float* b_qkv  = (const float*)d_in[5];
    const float* w_skip = (const float*)d_in[6];
    const float* b_skip = (const float*)d_in[7];
    const float* relb   = (const float*)d_in[8];
    const float* w_proj = (const float*)d_in[9];
    const float* b_proj = (const float*)d_in[10];
    const float* n2g    = (const float*)d_in[11];
    const float* n2b    = (const float*)d_in[12];
    const float* w_fc1  = (const float*)d_in[13];
    const float* b_fc1  = (const float*)d_in[14];
    const float* w_fc2  = (const float*)d_in[15];
    const float* b_fc2  = (const float*)d_in[16];
    float* outp = (float*)d_out;

    __half *axA, *asA, *hA, *wqB, *wsB, *wpB, *w1B, *w2B, *kvb, *qb;
    float *xres;
    cudaGetSymbolAddress((void**)&axA, g_axA);
    cudaGetSymbolAddress((void**)&asA, g_asA);
    cudaGetSymbolAddress((void**)&kvb, g_kv);
    cudaGetSymbolAddress((void**)&qb,  g_q);
    cudaGetSymbolAddress((void**)&xres, g_xres);
    cudaGetSymbolAddress((void**)&hA,  g_hA);
    cudaGetSymbolAddress((void**)&wqB, g_wqkvB);
    cudaGetSymbolAddress((void**)&wsB, g_wskipB);
    cudaGetSymbolAddress((void**)&wpB, g_wprojB);
    cudaGetSymbolAddress((void**)&w1B, g_wfc1B);
    cudaGetSymbolAddress((void**)&w2B, g_wfc2B);

    cudaFuncSetAttribute(gemm_h<0>, cudaFuncAttributeMaxDynamicSharedMemorySize, GEMM_SMEM);
    cudaFuncSetAttribute(gemm_h<1>, cudaFuncAttributeMaxDynamicSharedMemorySize, GEMM_SMEM);
    cudaFuncSetAttribute(gemm_h<2>, cudaFuncAttributeMaxDynamicSharedMemorySize, GEMM_SMEM);
    cudaFuncSetAttribute(gemm_h<3>, cudaFuncAttributeMaxDynamicSharedMemorySize, GEMM_SMEM);
    cudaFuncSetAttribute(gemm_h<4>, cudaFuncAttributeMaxDynamicSharedMemorySize, GEMM_SMEM);

    wconv_all<<<1536, 256>>>(w_qkv, w_skip, w_proj, w_fc1, w_fc2,
                             wqB, wsB, wpB, w1B, w2B);

    ln1_kernel<<<4096, 512>>>(x, skip, n1g, n1b, axA, asA);
    gemm_h<0><<<dim3(8, 256), 512, GEMM_SMEM>>>(axA, wqB, b_qkv, nullptr, nullptr, kvb, 1024, 512);
    gemm_h<1><<<dim3(4, 256), 512, GEMM_SMEM>>>(asA, wsB, b_skip, nullptr, nullptr, qb, 512, 512);
    attn_kernel<<<dim3(1024, 4), 256>>>(qb, kvb, relb, asA);
    gemm_h<2><<<dim3(4, 256), 512, GEMM_SMEM>>>(asA, wpB, b_proj, xres, x, nullptr, 512, 512);
    ln2_kernel<<<4096, 512>>>(xres, n2g, n2b, axA);
    gemm_h<3><<<dim3(16, 256), 512, GEMM_SMEM>>>(axA, w1B, b_fc1, nullptr, nullptr, hA, 2048, 512);
    gemm_h<4><<<dim3(4, 256), 512, GEMM_SMEM>>>(hA, w2B, b_fc2, outp, xres, nullptr, 512, 2048);
    (void)in_sizes; (void)n_in; (void)out_size;
}